// round 14
// baseline (speedup 1.0000x reference)
#include <cuda_runtime.h>
#include <cuda_bf16.h>
#include <cstdint>

#define NNODES 50000
#define NEDGES 800000
#define ND     64
#define H      128
#define OUTD   64
#define BN_EPS 1e-5f
#define NTILES2 (NEDGES / 128)             // 6250
#define NODE_TILES ((NNODES + 127) / 128)  // 391

// ---------------- scratch (device globals; no allocations allowed) ----------
__device__ float g_h1[(size_t)NEDGES * H];
__device__ float g_agg[(size_t)NNODES * H];
__device__ float g_h2[(size_t)NNODES * H];
__device__ float g_sum[H];
__device__ float g_sumsq[H];
__device__ float g_scale[H];
__device__ float g_shift[H];
// pre-split transposed weights: word (n, kpair) = bf16{k even}|bf16{k odd}<<16
__device__ __align__(16) uint32_t g_W1T_hi[128 * 64];
__device__ __align__(16) uint32_t g_W1T_lo[128 * 64];
__device__ __align__(16) uint32_t g_W2T_hi[128 * 64];
__device__ __align__(16) uint32_t g_W2T_lo[128 * 64];
__device__ __align__(16) uint32_t g_W3T_hi[128 * 96];   // W1b (K=192)
__device__ __align__(16) uint32_t g_W3T_lo[128 * 96];
__device__ __align__(16) uint32_t g_W4T_hi[64 * 64];    // W2b (K=128, N=64)
__device__ __align__(16) uint32_t g_W4T_lo[64 * 64];

// ---------------- helpers ----------------------------------------------------
__device__ __forceinline__ void split2(float a, float b, uint32_t& hi, uint32_t& lo) {
    __nv_bfloat16 ah = __float2bfloat16_rn(a), bh = __float2bfloat16_rn(b);
    float ar = a - __bfloat162float(ah);
    float br = b - __bfloat162float(bh);
    __nv_bfloat16 al = __float2bfloat16_rn(ar), bl = __float2bfloat16_rn(br);
    hi = (uint32_t)__bfloat16_as_ushort(ah) | ((uint32_t)__bfloat16_as_ushort(bh) << 16);
    lo = (uint32_t)__bfloat16_as_ushort(al) | ((uint32_t)__bfloat16_as_ushort(bl) << 16);
}

__device__ __forceinline__ void mma4(float* c, const uint32_t* a, uint32_t b0, uint32_t b1) {
    asm volatile(
        "mma.sync.aligned.m16n8k16.row.col.f32.bf16.bf16.f32 "
        "{%0,%1,%2,%3}, {%4,%5,%6,%7}, {%8,%9}, {%0,%1,%2,%3};"
        : "+f"(c[0]), "+f"(c[1]), "+f"(c[2]), "+f"(c[3])
        : "r"(a[0]), "r"(a[1]), "r"(a[2]), "r"(a[3]), "r"(b0), "r"(b1));
}

__device__ __forceinline__ void ldsm4(uint32_t* r, uint32_t addr) {
    asm volatile("ldmatrix.sync.aligned.m8n8.x4.shared.b16 {%0,%1,%2,%3}, [%4];"
                 : "=r"(r[0]), "=r"(r[1]), "=r"(r[2]), "=r"(r[3]) : "r"(addr));
}

__device__ __forceinline__ uint32_t smaddr(const void* p) {
    return (uint32_t)__cvta_generic_to_shared(p);
}

__device__ __forceinline__ void red_add_v4(float* p, float a, float b, float c, float d) {
    asm volatile("red.global.add.v4.f32 [%0], {%1,%2,%3,%4};"
                 :: "l"(p), "f"(a), "f"(b), "f"(c), "f"(d) : "memory");
}

#define SK 20    // smem stride words (16 kpairs + 4 pad); LDSM-conflict-free

// One k32 chunk of bf16x3 MMA via ldmatrix feeds (proven routine).
__device__ __forceinline__ void mma_chunk_ldsm(
    uint32_t aH0, uint32_t aH1, uint32_t aL0, uint32_t aL1,
    uint32_t bH0, uint32_t bH1, uint32_t bL0, uint32_t bL1,
    float acc[2][4][4]) {
#pragma unroll
    for (int kc = 0; kc < 2; kc++) {
        const uint32_t kb = kc * 32;
        uint32_t a0[4], a1[4], b0[4], b1[4];
        ldsm4(a0, aH0 + kb); ldsm4(a1, aH1 + kb);
        ldsm4(b0, bH0 + kb); ldsm4(b1, bH1 + kb);
        mma4(acc[0][0], a0, b0[0], b0[2]); mma4(acc[0][1], a0, b0[1], b0[3]);
        mma4(acc[0][2], a0, b1[0], b1[2]); mma4(acc[0][3], a0, b1[1], b1[3]);
        mma4(acc[1][0], a1, b0[0], b0[2]); mma4(acc[1][1], a1, b0[1], b0[3]);
        mma4(acc[1][2], a1, b1[0], b1[2]); mma4(acc[1][3], a1, b1[1], b1[3]);
        uint32_t c0[4], c1[4];
        ldsm4(c0, bL0 + kb); ldsm4(c1, bL1 + kb);
        mma4(acc[0][0], a0, c0[0], c0[2]); mma4(acc[0][1], a0, c0[1], c0[3]);
        mma4(acc[0][2], a0, c1[0], c1[2]); mma4(acc[0][3], a0, c1[1], c1[3]);
        mma4(acc[1][0], a1, c0[0], c0[2]); mma4(acc[1][1], a1, c0[1], c0[3]);
        mma4(acc[1][2], a1, c1[0], c1[2]); mma4(acc[1][3], a1, c1[1], c1[3]);
        uint32_t d0[4], d1[4];
        ldsm4(d0, aL0 + kb); ldsm4(d1, aL1 + kb);
        mma4(acc[0][0], d0, b0[0], b0[2]); mma4(acc[0][1], d0, b0[1], b0[3]);
        mma4(acc[0][2], d0, b1[0], b1[2]); mma4(acc[0][3], d0, b1[1], b1[3]);
        mma4(acc[1][0], d1, b0[0], b0[2]); mma4(acc[1][1], d1, b0[1], b0[3]);
        mma4(acc[1][2], d1, b1[0], b1[2]); mma4(acc[1][3], d1, b1[1], b1[3]);
    }
}

// ---------------- merged prep: zero agg/stats + all 4 weight splits ----------
__global__ void prep_kernel(const float* __restrict__ W1a,
                            const float* __restrict__ W2a,
                            const float* __restrict__ W1b,
                            const float* __restrict__ W2b) {
    int i = blockIdx.x * blockDim.x + threadIdx.x;
    const float4 z = {0.f, 0.f, 0.f, 0.f};
    if (i < NNODES * H / 4) ((float4*)g_agg)[i] = z;
    if (i < H / 4) { ((float4*)g_sum)[i] = z; ((float4*)g_sumsq)[i] = z; }
    if (i < 8192) {
        int n = i >> 6, kp = i & 63;
        uint32_t h, l;
        split2(W1a[(2 * kp) * 128 + n], W1a[(2 * kp + 1) * 128 + n], h, l);
        g_W1T_hi[i] = h; g_W1T_lo[i] = l;
    } else if (i < 16384) {
        int j = i - 8192, n = j >> 6, kp = j & 63;
        uint32_t h, l;
        split2(W2a[(2 * kp) * 128 + n], W2a[(2 * kp + 1) * 128 + n], h, l);
        g_W2T_hi[j] = h; g_W2T_lo[j] = l;
    } else if (i < 28672) {
        int j = i - 16384, n = j / 96, kp = j - n * 96;
        uint32_t h, l;
        split2(W1b[(2 * kp) * 128 + n], W1b[(2 * kp + 1) * 128 + n], h, l);
        g_W3T_hi[j] = h; g_W3T_lo[j] = l;
    } else if (i < 32768) {
        int j = i - 28672, n = j >> 6, kp = j & 63;
        uint32_t h, l;
        split2(W2b[(2 * kp) * OUTD + n], W2b[(2 * kp + 1) * OUTD + n], h, l);
        g_W4T_hi[j] = h; g_W4T_lo[j] = l;
    }
}

__global__ void finalize_bn(const float* __restrict__ gamma,
                            const float* __restrict__ beta, float invM) {
    int c = threadIdx.x;
    float mean = g_sum[c] * invM;
    float var  = g_sumsq[c] * invM - mean * mean;
    float sc   = gamma[c] * rsqrtf(var + BN_EPS);
    g_scale[c] = sc;
    g_shift[c] = beta[c] - mean * sc;
    g_sum[c] = 0.f; g_sumsq[c] = 0.f;
}

// ============================================================================
// Edge GEMM1: depth-2 A prefetch (va banks), depth-1 B prefetch.
// ============================================================================
__global__ __launch_bounds__(512, 1) void edge_mma1(
    const float* __restrict__ x, const int* __restrict__ ei,
    const float* __restrict__ ea, const float* __restrict__ bias) {
    __shared__ uint32_t sAh[128 * SK], sAl[128 * SK];
    __shared__ uint32_t sBh[128 * SK], sBl[128 * SK];
    __shared__ int rowidx[128];
    __shared__ float s_bias[128];
    __shared__ float red_s[4][128], red_q[4][128];

    const int t = threadIdx.x, tile = blockIdx.x;
    if (t < 128) { rowidx[t] = ei[tile * 128 + t]; s_bias[t] = bias[t]; }
    __syncthreads();

    const int warp = t >> 5, lane = t & 31, g = lane >> 2, t4 = lane & 3;
    const int wm = (warp >> 2) * 32, wn = (warp & 3) * 32;
    const int m = t >> 2, q = t & 3;
    const int n = t >> 2, qb = t & 3;

    const int rA = (lane & 7) + ((lane >> 3) & 1) * 8;
    const int cH = (lane >> 4) * 4;
    const uint32_t aH0 = smaddr(&sAh[(wm + rA) * SK + cH]);
    const uint32_t aH1 = smaddr(&sAh[(wm + 16 + rA) * SK + cH]);
    const uint32_t aL0 = smaddr(&sAl[(wm + rA) * SK + cH]);
    const uint32_t aL1 = smaddr(&sAl[(wm + 16 + rA) * SK + cH]);
    const int rB = lane & 15;
    const uint32_t bH0 = smaddr(&sBh[(wn + rB) * SK + cH]);
    const uint32_t bH1 = smaddr(&sBh[(wn + 16 + rB) * SK + cH]);
    const uint32_t bL0 = smaddr(&sBl[(wn + rB) * SK + cH]);
    const uint32_t bL1 = smaddr(&sBl[(wn + 16 + rB) * SK + cH]);

    float acc[2][4][4];
#pragma unroll
    for (int i = 0; i < 2; i++)
#pragma unroll
        for (int j = 0; j < 4; j++)
#pragma unroll
            for (int k = 0; k < 4; k++) acc[i][j][k] = 0.f;

    // A source pointer for chunk s (k = s*32 + q*8)
    auto srcA = [&](int s) -> const float* {
        int kb = s * 32 + q * 8;
        return (s < 2) ? (x + (size_t)rowidx[m] * ND + kb)
                       : (ea + (size_t)(tile * 128 + m) * ND + (kb - 64));
    };

    float4 va[2][2];   // two A prefetch banks
    uint4 qh, ql;
    {
        const float* p0 = srcA(0);
        va[0][0] = ((const float4*)p0)[0]; va[0][1] = ((const float4*)p0)[1];
        const float* p1 = srcA(1);
        va[1][0] = ((const float4*)p1)[0]; va[1][1] = ((const float4*)p1)[1];
        qh = *(const uint4*)&g_W1T_hi[n * 64 + qb * 4];
        ql = *(const uint4*)&g_W1T_lo[n * 64 + qb * 4];
    }

#pragma unroll
    for (int s = 0; s < 4; s++) {
        const int bk = s & 1;
        {   // store A chunk s from its bank
            uint32_t h0, l0, h1, l1, h2, l2, h3, l3;
            split2(va[bk][0].x, va[bk][0].y, h0, l0);
            split2(va[bk][0].z, va[bk][0].w, h1, l1);
            split2(va[bk][1].x, va[bk][1].y, h2, l2);
            split2(va[bk][1].z, va[bk][1].w, h3, l3);
            *(uint4*)&sAh[m * SK + q * 4] = make_uint4(h0, h1, h2, h3);
            *(uint4*)&sAl[m * SK + q * 4] = make_uint4(l0, l1, l2, l3);
        }
        {
            *(uint4*)&sBh[n * SK + qb * 4] = qh;
            *(uint4*)&sBl[n * SK + qb * 4] = ql;
        }
        __syncthreads();
        if (s + 2 < 4) {   // depth-2 A prefetch into the freed bank
            const float* p = srcA(s + 2);
            va[bk][0] = ((const float4*)p)[0]; va[bk][1] = ((const float4*)p)[1];
        }
        if (s + 1 < 4) {   // depth-1 B prefetch (L2-hot)
            qh = *(const uint4*)&g_W1T_hi[n * 64 + (s + 1) * 16 + qb * 4];
            ql = *(const uint4*)&g_W1T_lo[n * 64 + (s + 1) * 16 + qb * 4];
        }
        mma_chunk_ldsm(aH0, aH1, aL0, aL1, bH0, bH1, bL0, bL1, acc);
        __syncthreads();
    }

    float s8[8] = {0, 0, 0, 0, 0, 0, 0, 0}, q8[8] = {0, 0, 0, 0, 0, 0, 0, 0};
    const int odd = t4 & 1;
#pragma unroll
    for (int mt = 0; mt < 2; mt++) {
        int r0 = wm + mt * 16 + g;
#pragma unroll
        for (int nt = 0; nt < 4; nt++) {
            int c = wn + nt * 8 + 2 * t4;
            float bx = s_bias[c], by = s_bias[c + 1];
            float v00 = acc[mt][nt][0] + bx, v01 = acc[mt][nt][1] + by;
            float v10 = acc[mt][nt][2] + bx, v11 = acc[mt][nt][3] + by;
            s8[nt * 2]     += v00 + v10;
            s8[nt * 2 + 1] += v01 + v11;
            q8[nt * 2]     += v00 * v00 + v10 * v10;
            q8[nt * 2 + 1] += v01 * v01 + v11 * v11;
            float e0 = odd ? v00 : v10;
            float e1 = odd ? v01 : v11;
            float p0 = __shfl_xor_sync(0xffffffffu, e0, 1);
            float p1 = __shfl_xor_sync(0xffffffffu, e1, 1);
            int row = r0 + odd * 8;
            int cb  = wn + nt * 8 + (t4 & 2) * 2;
            float4 quad = odd ? make_float4(p0, p1, v10, v11)
                              : make_float4(v00, v01, p0, p1);
            *(float4*)&g_h1[(size_t)(tile * 128 + row) * H + cb] = quad;
        }
    }
#pragma unroll
    for (int j = 0; j < 8; j++)
#pragma unroll
        for (int o = 4; o < 32; o <<= 1) {
            s8[j] += __shfl_xor_sync(0xffffffffu, s8[j], o);
            q8[j] += __shfl_xor_sync(0xffffffffu, q8[j], o);
        }
    if (lane < 4) {
        int wr = warp >> 2;
#pragma unroll
        for (int nt = 0; nt < 4; nt++) {
            red_s[wr][wn + nt * 8 + 2 * lane]     = s8[nt * 2];
            red_s[wr][wn + nt * 8 + 2 * lane + 1] = s8[nt * 2 + 1];
            red_q[wr][wn + nt * 8 + 2 * lane]     = q8[nt * 2];
            red_q[wr][wn + nt * 8 + 2 * lane + 1] = q8[nt * 2 + 1];
        }
    }
    __syncthreads();
    if (t < 128) {
        atomicAdd(&g_sum[t],   red_s[0][t] + red_s[1][t] + red_s[2][t] + red_s[3][t]);
        atomicAdd(&g_sumsq[t], red_q[0][t] + red_q[1][t] + red_q[2][t] + red_q[3][t]);
    }
}

// ============================================================================
// Edge GEMM2 + scatter: depth-2 A prefetch.
// ============================================================================
__global__ __launch_bounds__(512, 1) void edge_mma2(
    const int* __restrict__ ei, const float* __restrict__ bias) {
    __shared__ uint32_t sAh[128 * SK], sAl[128 * SK];
    __shared__ uint32_t sBh[128 * SK], sBl[128 * SK];
    __shared__ int colidx[128];
    __shared__ float s_bias[128], s_sc[128], s_sh[128];

    const int t = threadIdx.x, tile = blockIdx.x;
    if (t < 128) {
        colidx[t] = ei[NEDGES + tile * 128 + t];
        s_bias[t] = bias[t];
        s_sc[t] = g_scale[t];
        s_sh[t] = g_shift[t];
    }
    __syncthreads();

    const int warp = t >> 5, lane = t & 31, g = lane >> 2, t4 = lane & 3;
    const int wm = (warp >> 2) * 32, wn = (warp & 3) * 32;
    const int m = t >> 2, q = t & 3;
    const int n = t >> 2, qb = t & 3;

    const int rA = (lane & 7) + ((lane >> 3) & 1) * 8;
    const int cH = (lane >> 4) * 4;
    const uint32_t aH0 = smaddr(&sAh[(wm + rA) * SK + cH]);
    const uint32_t aH1 = smaddr(&sAh[(wm + 16 + rA) * SK + cH]);
    const uint32_t aL0 = smaddr(&sAl[(wm + rA) * SK + cH]);
    const uint32_t aL1 = smaddr(&sAl[(wm + 16 + rA) * SK + cH]);
    const int rB = lane & 15;
    const uint32_t bH0 = smaddr(&sBh[(wn + rB) * SK + cH]);
    const uint32_t bH1 = smaddr(&sBh[(wn + 16 + rB) * SK + cH]);
    const uint32_t bL0 = smaddr(&sBl[(wn + rB) * SK + cH]);
    const uint32_t bL1 = smaddr(&sBl[(wn + 16 + rB) * SK + cH]);

    float acc[2][4][4];
#pragma unroll
    for (int i = 0; i < 2; i++)
#pragma unroll
        for (int j = 0; j < 4; j++)
#pragma unroll
            for (int k = 0; k < 4; k++) acc[i][j][k] = 0.f;

    float4 va[2][2];
    uint4 qh, ql;
    {
        const float* base = g_h1 + (size_t)(tile * 128 + m) * H + q * 8;
        va[0][0] = ((const float4*)base)[0];      va[0][1] = ((const float4*)base)[1];
        va[1][0] = ((const float4*)(base + 32))[0]; va[1][1] = ((const float4*)(base + 32))[1];
        qh = *(const uint4*)&g_W2T_hi[n * 64 + qb * 4];
        ql = *(const uint4*)&g_W2T_lo[n * 64 + qb * 4];
    }

#pragma unroll
    for (int s = 0; s < 4; s++) {
        const int bk = s & 1;
        {   // BN + relu + split + store A chunk s
            int kb = s * 32 + q * 8;
            float4 v0 = va[bk][0], v1 = va[bk][1];
            v0.x = fmaxf(fmaf(v0.x, s_sc[kb],     s_sh[kb]),     0.f);
            v0.y = fmaxf(fmaf(v0.y, s_sc[kb + 1], s_sh[kb + 1]), 0.f);
            v0.z = fmaxf(fmaf(v0.z, s_sc[kb + 2], s_sh[kb + 2]), 0.f);
            v0.w = fmaxf(fmaf(v0.w, s_sc[kb + 3], s_sh[kb + 3]), 0.f);
            v1.x = fmaxf(fmaf(v1.x, s_sc[kb + 4], s_sh[kb + 4]), 0.f);
            v1.y = fmaxf(fmaf(v1.y, s_sc[kb + 5], s_sh[kb + 5]), 0.f);
            v1.z = fmaxf(fmaf(v1.z, s_sc[kb + 6], s_sh[kb + 6]), 0.f);
            v1.w = fmaxf(fmaf(v1.w, s_sc[kb + 7], s_sh[kb + 7]), 0.f);
            uint32_t h0, l0, h1, l1, h2, l2, h3, l3;
            split2(v0.x, v0.y, h0, l0); split2(v0.z, v0.w, h1, l1);
            split2(v1.x, v1.y, h2, l2); split2(v1.z, v1.w, h3, l3);
            *(uint4*)&sAh[m * SK + q * 4] = make_uint4(h0, h1, h2, h3);
            *(uint4*)&sAl[m * SK + q * 4] = make_uint4(l0, l1, l2, l3);
        }
        {
            *(uint4*)&sBh[n * SK + qb * 4] = qh;
            *(uint4*)&sBl[n * SK + qb * 4] = ql;
        }
        __syncthreads();
        if (s + 2 < 4) {
            const float* p = g_h1 + (size_t)(tile * 128 + m) * H + (s + 2) * 32 + q * 8;
            va[bk][0] = ((const float4*)p)[0]; va[bk][1] = ((const float4*)p)[1];
        }
        if (s + 1 < 4) {
            qh = *(const uint4*)&g_W2T_hi[n * 64 + (s + 1) * 16 + qb * 4];
            ql = *(const uint4*)&g_W2T_lo[n * 64 + (s + 1) * 16 + qb * 4];
        }
        mma_chunk_ldsm(aH0, aH1, aL0, aL1, bH0, bH1, bL0, bL1, acc);
        __syncthreads();
    }

    const int odd = t4 & 1;
#pragma unroll
    for (int mt = 0; mt < 2; mt++) {
        int r0 = wm + mt * 16 + g;
#pragma unroll
        for (int nt = 0; nt < 4; nt++) {
            int c = wn + nt * 8 + 2 * t4;
            float bx = s_bias[c], by = s_bias[c + 1];
            float v00 = acc[mt][nt][0] + bx, v01 = acc[mt][nt][1] + by;
            float v10 = acc[mt][nt][2] + bx, v11 = acc[mt][nt][3] + by;
            float e0 = odd ? v00 : v10;
            float e1 = odd ? v01 : v11;
            float p0 = __shfl_xor_sync(0xffffffffu, e0, 1);
            float p1 = __shfl_xor_sync(0xffffffffu, e1, 1);
            int row = r0 + odd * 8;
            int node = colidx[row];
            int cb  = wn + nt * 8 + (t4 & 2) * 2;
            if (odd)
                red_add_v4(&g_agg[(size_t)node * H + cb], p0, p1, v10, v11);
            else
                red_add_v4(&g_agg[(size_t)node * H + cb], v00, v01, p0, p1);
        }
    }
}

// ============================================================================
// Node MMA1: depth-2 A prefetch (6 chunks).
// ============================================================================
__global__ __launch_bounds__(512, 1) void node_mma1(
    const float* __restrict__ x, const float* __restrict__ bias) {
    __shared__ uint32_t sAh[128 * SK], sAl[128 * SK];
    __shared__ uint32_t sBh[128 * SK], sBl[128 * SK];
    __shared__ float s_bias[128];
    __shared__ float red_s[4][128], red_q[4][128];

    const int t = threadIdx.x, tile = blockIdx.x;
    if (t < 128) s_bias[t] = bias[t];
    __syncthreads();

    const int warp = t >> 5, lane = t & 31, g = lane >> 2, t4 = lane & 3;
    const int wm = (warp >> 2) * 32, wn = (warp & 3) * 32;
    const int m = t >> 2, q = t & 3;
    const int n = t >> 2, qb = t & 3;
    const int grow = tile * 128 + m;
    const bool rok = grow < NNODES;

    const int rA = (lane & 7) + ((lane >> 3) & 1) * 8;
    const int cH = (lane >> 4) * 4;
    const uint32_t aH0 = smaddr(&sAh[(wm + rA) * SK + cH]);
    const uint32_t aH1 = smaddr(&sAh[(wm + 16 + rA) * SK + cH]);
    const uint32_t aL0 = smaddr(&sAl[(wm + rA) * SK + cH]);
    const uint32_t aL1 = smaddr(&sAl[(wm + 16 + rA) * SK + cH]);
    const int rB = lane & 15;
    const uint32_t bH0 = smaddr(&sBh[(wn + rB) * SK + cH]);
    const uint32_t bH1 = smaddr(&sBh[(wn + 16 + rB) * SK + cH]);
    const uint32_t bL0 = smaddr(&sBl[(wn + rB) * SK + cH]);
    const uint32_t bL1 = smaddr(&sBl[(wn + 16 + rB) * SK + cH]);

    float acc[2][4][4];
#pragma unroll
    for (int i = 0; i < 2; i++)
#pragma unroll
        for (int j = 0; j < 4; j++)
#pragma unroll
            for (int k = 0; k < 4; k++) acc[i][j][k] = 0.f;

    auto loadA = [&](int s, float4& v0, float4& v1) {
        if (!rok) { v0 = make_float4(0, 0, 0, 0); v1 = v0; return; }
        int k = s * 32 + q * 8;
        const float* src = (s < 2) ? (x + (size_t)grow * ND + k)
                                   : (g_agg + (size_t)grow * H + (k - 64));
        v0 = ((const float4*)src)[0]; v1 = ((const float4*)src)[1];
    };

    float4 va[2][2];
    uint4 qh, ql;
    loadA(0, va[0][0], va[0][1]);
    loadA(1, va[1][0], va[1][1]);
    qh = *(const uint4*)&g_W3T_hi[n * 96 + qb * 4];
    ql = *(const uint4*)&g_W3T_lo[n * 96 + qb * 4];

#pragma unroll
    for (int s = 0; s < 6; s++) {
        const int bk = s & 1;
        {
            uint32_t h0, l0, h1, l1, h2, l2, h3, l3;
            split2(va[bk][0].x, va[bk][0].y, h0, l0);
            split2(va[bk][0].z, va[bk][0].w, h1, l1);
            split2(va[bk][1].x, va[bk][1].y, h2, l2);
            split2(va[bk][1].z, va[bk][1].w, h3, l3);
            *(uint4*)&sAh[m * SK + q * 4] = make_uint4(h0, h1, h2, h3);
            *(uint4*)&sAl[m * SK + q * 4] = make_uint4(l0, l1, l2, l3);
        }
        {
            *(uint4*)&sBh[n * SK + qb * 4] = qh;
            *(uint4*)&sBl[n * SK + qb * 4] = ql;
        }
        __syncthreads();
        if (s + 2 < 6) loadA(s + 2, va[bk][0], va[bk][1]);
        if (s + 1 < 6) {
            qh = *(const uint4*)&g_W3T_hi[n * 96 + (s + 1) * 16 + qb * 4];
            ql = *(const uint4*)&g_W3T_lo[n * 96 + (s + 1) * 16 + qb * 4];
        }
        mma_chunk_ldsm(aH0, aH1, aL0, aL1, bH0, bH1, bL0, bL1, acc);
        __syncthreads();
    }

    float s8[8] = {0, 0, 0, 0, 0, 0, 0, 0}, q8[8] = {0, 0, 0, 0, 0, 0, 0, 0};
#pragma unroll
    for (int mt = 0; mt < 2; mt++) {
        int r0 = wm + mt * 16 + g;
        int n0 = tile * 128 + r0, n1 = n0 + 8;
        bool ok0 = n0 < NNODES, ok1 = n1 < NNODES;
#pragma unroll
        for (int nt = 0; nt < 4; nt++) {
            int c = wn + nt * 8 + 2 * t4;
            float bx = s_bias[c], by = s_bias[c + 1];
            float v00 = acc[mt][nt][0] + bx, v01 = acc[mt][nt][1] + by;
            float v10 = acc[mt][nt][2] + bx, v11 = acc[mt][nt][3] + by;
            if (ok0) {
                float2 w0 = {v00, v01};
                *(float2*)&g_h2[(size_t)n0 * H + c] = w0;
                s8[nt * 2] += v00; s8[nt * 2 + 1] += v01;
                q8[nt * 2] += v00 * v00; q8[nt * 2 + 1] += v01 * v01;
            }
            if (ok1) {
                float2 w1 = {v10, v11};
                *(float2*)&g_h2[(size_t)n1 * H + c] = w1;
                s8[nt * 2] += v10; s8[nt * 2 + 1] += v11;
                q8[nt * 2] += v10 * v10; q8[nt * 2 + 1] += v11 * v11;
            }
        }
    }
#pragma unroll
    for (int j = 0; j < 8; j++)
#pragma unroll
        for (int o = 4; o < 32; o <<= 1) {
            s8[j] += __shfl_xor_sync(0xffffffffu, s8[j], o);
            q8[j] += __shfl_xor_sync(0xffffffffu, q8[j], o);
        }
    if (lane < 4) {
        int wr = warp >> 2;
#pragma unroll
        for (int nt = 0; nt < 4; nt++) {
            red_s[wr][wn + nt * 8 + 2 * lane]     = s8[nt * 2];
            red_s[wr][wn + nt * 8 + 2 * lane + 1] = s8[nt * 2 + 1];
            red_q[wr][wn + nt * 8 + 2 * lane]     = q8[nt * 2];
            red_q[wr][wn + nt * 8 + 2 * lane + 1] = q8[nt * 2 + 1];
        }
    }
    __syncthreads();
    if (t < 128) {
        atomicAdd(&g_sum[t],   red_s[0][t] + red_s[1][t] + red_s[2][t] + red_s[3][t]);
        atomicAdd(&g_sumsq[t], red_q[0][t] + red_q[1][t] + red_q[2][t] + red_q[3][t]);
    }
}

// ============================================================================
// Node MMA2 (round-13 proven, verbatim)
// ============================================================================
__global__ __launch_bounds__(256, 2) void node_mma2(
    const float* __restrict__ bias, float* __restrict__ out) {
    __shared__ uint32_t sAh[128 * SK], sAl[128 * SK];
    __shared__ uint32_t sBh[64 * SK], sBl[64 * SK];
    __shared__ float s_bias[64], s_sc[128], s_sh[128];

    const int t = threadIdx.x, tile = blockIdx.x;
    if (t < 64) s_bias[t] = bias[t];
    if (t < 128) { s_sc[t] = g_scale[t]; s_sh[t] = g_shift[t]; }
    __syncthreads();

    const int warp = t >> 5, lane = t & 31, g = lane >> 2, t4 = lane & 3;
    const int wm = (warp >> 1) * 32, wn = (warp & 1) * 32;
    const int m = t >> 1, q2 = t & 1;
    const int n = t >> 2, qb = t & 3;
    const int grow = tile * 128 + m;
    const bool rok = grow < NNODES;

    const int rA = (lane & 7) + ((lane >> 3) & 1) * 8;
    const int cH = (lane >> 4) * 4;
    const uint32_t aH0 = smaddr(&sAh[(wm + rA) * SK + cH]);
    const uint32_t aH1 = smaddr(&sAh[(wm + 16 + rA) * SK + cH]);
    const uint32_t aL0 = smaddr(&sAl[(wm + rA) * SK + cH]);
    const uint32_t aL1 = smaddr(&sAl[(wm + 16 + rA) * SK + cH]);
    const int rB = lane & 15;
    const uint32_t bH0 = smaddr(&sBh[(wn + rB) * SK + cH]);
    const uint32_t bH1 = smaddr(&sBh[(wn + 16 + rB) * SK + cH]);
    const uint32_t bL0 = smaddr(&sBl[(wn + rB) * SK + cH]);
    const uint32_t bL1 = smaddr(&sBl[(wn + 16 + rB) * SK + cH]);

    float acc[2][4][4];
#pragma unroll
    for (int i = 0; i < 2; i++)
#pragma unroll
        for (int j = 0; j < 4; j++)
#pragma unroll
            for (int k = 0; k < 4; k++) acc[i][j][k] = 0.f;

    float4 va0, va1, va2, va3;
    uint4 qh, ql;
    auto loadA = [&](int s) {
        if (!rok) { va0 = make_float4(0, 0, 0, 0); va1 = va0; va2 = va0; va3 = va0; return; }
        const float* src = g_h2 + (size_t)grow * H + s * 32 + q2 * 16;
        va0 = ((const float4*)src)[0]; va1 = ((const float4*)src)[1];
        va2 = ((const float4*)src)[2]; va3 = ((const float4*)src)[3];
    };
    auto storeA = [&](int s) {
        int kb = s * 32 + q2 * 16;
        float4 v[4] = {va0, va1, va2, va3};
#pragma unroll
        for (int j = 0; j < 4; j++) {
            int k = kb + 4 * j;
            v[j].x = fmaxf(fmaf(v[j].x, s_sc[k],     s_sh[k]),     0.f);
            v[j].y = fmaxf(fmaf(v[j].y, s_sc[k + 1], s_sh[k + 1]), 0.f);
            v[j].z = fmaxf(fmaf(v[j].z, s_sc[k + 2], s_sh[k + 2]), 0.f);
            v[j].w = fmaxf(fmaf(v[j].w, s_sc[k + 3], s_sh[k + 3]), 0.f);
        }
        uint32_t h[8], l[8];
#pragma unroll
        for (int j = 0; j < 4; j++) {
            split2(v[j].x, v[j].y, h[2 * j], l[2 * j]);
            split2(v[j].z, v[j].w, h[2 * j + 1], l[2 * j + 1]);
        }
        *(uint4*)&sAh[m * SK + q2 * 8]     = make_uint4(h[0], h[1], h[2], h[3]);
        *(uint4*)&sAh[m * SK + q2 * 8 + 4] = make_uint4(h[4], h[5], h[6], h[7]);
        *(uint4*)&sAl[m * SK + q2 * 8]     = make_uint4(l[0], l[1], l[2], l[3]);
        *(uint4*)&sAl[m * SK + q2 * 8 + 4] = make_uint4(l[4], l[5], l[6], l[7]);
    };

    loadA(0);
    qh = *(const uint4*)&g_W4T_hi[n * 64 + qb * 4];
    ql = *(const uint4*)&g_W4T_lo[n * 64 + qb * 4];

#pragma unroll
    for (int s = 0; s < 4; s++) {
        storeA(s);
        *(uint4*)&sBh[n * SK + qb * 4] = qh;
        *(uint4*)&sBl[n * SK + qb * 4] = ql;
        __syncthreads();
        if (s < 3) {
            loadA(s + 1);
            qh = *(const uint4*)&g_W4T_hi[n * 64 + (s + 1) * 16 + qb * 4];
            ql = *(const uint4*)&g_W4T_lo[n * 64 + (s + 1) * 16 + qb * 4];
        }
        mma_chunk_ldsm(aH0, aH1, aL0, aL1, bH0, bH1, bL0, bL1, acc);
        __syncthreads();
    }

    const int odd = t4 & 1;
#pragma unroll
    for (int mt = 0; mt < 2; mt++) {
        int r0 = wm + mt * 16 + g;
#pragma unroll
        for (int nt = 0; nt < 4; nt++) {
            int c = wn + nt * 8 + 2 * t4;
            float bx = s_bias[c], by = s_bias[c + 1];
            float v00 = acc[mt][nt][0] + bx, v01 = acc[mt][nt][1] + by;
            float v10 = acc[mt][nt][2] + bx, v11 = acc[mt][nt][3] + by;
            float e0 = odd ? v00 : v10;
            float e1 = odd ? v01 : v11;
            float p0 = __shfl_xor_sync(0xffffffffu, e0, 1);
            float p1 = __shfl_xor_sync(0xffffffffu, e1, 1);
            int row = r0 + odd * 8;
            int gn = tile * 128 + row;
            int cb = wn + nt * 8 + (t4 & 2) * 2;
            float4 quad = odd ? make_float4(p0, p1, v10, v11)
                              : make_float4(v00, v01, p0, p1);
            if (gn < NNODES)
                *(float4*)&out[(size_t)gn * OUTD + cb] = quad;
        }
    }
}

// ============================================================================
extern "C" void kernel_launch(void* const* d_in, const int* in_sizes, int n_in,
                              void* d_out, int out_size) {
    const float* x    = (const float*)d_in[0];
    const int*   ei   = (const int*)d_in[1];
    const float* ea   = (const float*)d_in[2];
    const float* W1a  = (const float*)d_in[5];
    const float* b1a  = (const float*)d_in[6];
    const float* g1a  = (const float*)d_in[7];
    const float* be1a = (const float*)d_in[8];
    const float* W2a  = (const float*)d_in[9];
    const float* b2a  = (const float*)d_in[10];
    const float* W1b  = (const float*)d_in[11];
    const float* b1b  = (const float*)d_in[12];
    const float* g1b  = (const float*)d_in[13];
    const float* be1b = (const float*)d_in[14];
    const float* W2b  = (const float*)d_in[15];
    const float* b2b  = (const float*)d_in[16];
    float* out = (float*)d_out;

    prep_kernel<<<(NNODES * H / 4 + 255) / 256, 256>>>(W1a, W2a, W1b, W2b);
    edge_mma1<<<NTILES2, 512>>>(x, ei, ea, b1a);
    finalize_bn<<<1, 128>>>(g1a, be1a, 1.0f / (float)NEDGES);
    edge_mma2<<<NTILES2, 512>>>(ei, b2a);
    node_mma1<<<NODE_TILES, 512>>>(x, b1b);
    finalize_bn<<<1, 128>>>(g1b, be1b, 1.0f / (float)NNODES);
    node_mma2<<<NODE_TILES, 256>>>(b2b, out);
}

// round 15
// speedup vs baseline: 1.1492x; 1.1492x over previous
#include <cuda_runtime.h>
#include <cuda_bf16.h>
#include <cuda_fp16.h>
#include <cstdint>

#define NNODES 50000
#define NEDGES 800000
#define ND     64
#define H      128
#define OUTD   64
#define BN_EPS 1e-5f
#define NTILES2 (NEDGES / 128)             // 6250
#define NODE_TILES ((NNODES + 127) / 128)  // 391

// ---------------- scratch (device globals; no allocations allowed) ----------
__device__ float g_h1[(size_t)NEDGES * H];
__device__ float g_agg[(size_t)NNODES * H];
__device__ float g_h2[(size_t)NNODES * H];
__device__ float g_sum[H];
__device__ float g_sumsq[H];
__device__ float g_scale[H];
__device__ float g_shift[H];
// edge weights: fp16 hi only (fp16x2 scheme). word(n,kpair) = f16{k}|f16{k+1}<<16
__device__ __align__(16) uint32_t g_W1T_hi[128 * 64];
__device__ __align__(16) uint32_t g_W2T_hi[128 * 64];
// node weights: bf16 hi/lo (bf16x3 scheme)
__device__ __align__(16) uint32_t g_W3T_hi[128 * 96];
__device__ __align__(16) uint32_t g_W3T_lo[128 * 96];
__device__ __align__(16) uint32_t g_W4T_hi[64 * 64];
__device__ __align__(16) uint32_t g_W4T_lo[64 * 64];

// ---------------- helpers ----------------------------------------------------
__device__ __forceinline__ void split2(float a, float b, uint32_t& hi, uint32_t& lo) {
    __nv_bfloat16 ah = __float2bfloat16_rn(a), bh = __float2bfloat16_rn(b);
    float ar = a - __bfloat162float(ah);
    float br = b - __bfloat162float(bh);
    __nv_bfloat16 al = __float2bfloat16_rn(ar), bl = __float2bfloat16_rn(br);
    hi = (uint32_t)__bfloat16_as_ushort(ah) | ((uint32_t)__bfloat16_as_ushort(bh) << 16);
    lo = (uint32_t)__bfloat16_as_ushort(al) | ((uint32_t)__bfloat16_as_ushort(bl) << 16);
}

// fp16 split: hi = f16(a,b), lo = f16 residuals
__device__ __forceinline__ void split2h(float a, float b, uint32_t& hi, uint32_t& lo) {
    __half ah = __float2half_rn(a), bh = __float2half_rn(b);
    float ar = a - __half2float(ah);
    float br = b - __half2float(bh);
    __half al = __float2half_rn(ar), bl = __float2half_rn(br);
    hi = (uint32_t)__half_as_ushort(ah) | ((uint32_t)__half_as_ushort(bh) << 16);
    lo = (uint32_t)__half_as_ushort(al) | ((uint32_t)__half_as_ushort(bl) << 16);
}
__device__ __forceinline__ uint32_t packh(float a, float b) {
    __half ah = __float2half_rn(a), bh = __float2half_rn(b);
    return (uint32_t)__half_as_ushort(ah) | ((uint32_t)__half_as_ushort(bh) << 16);
}

__device__ __forceinline__ void mma4(float* c, const uint32_t* a, uint32_t b0, uint32_t b1) {
    asm volatile(
        "mma.sync.aligned.m16n8k16.row.col.f32.bf16.bf16.f32 "
        "{%0,%1,%2,%3}, {%4,%5,%6,%7}, {%8,%9}, {%0,%1,%2,%3};"
        : "+f"(c[0]), "+f"(c[1]), "+f"(c[2]), "+f"(c[3])
        : "r"(a[0]), "r"(a[1]), "r"(a[2]), "r"(a[3]), "r"(b0), "r"(b1));
}
__device__ __forceinline__ void mma4h(float* c, const uint32_t* a, uint32_t b0, uint32_t b1) {
    asm volatile(
        "mma.sync.aligned.m16n8k16.row.col.f32.f16.f16.f32 "
        "{%0,%1,%2,%3}, {%4,%5,%6,%7}, {%8,%9}, {%0,%1,%2,%3};"
        : "+f"(c[0]), "+f"(c[1]), "+f"(c[2]), "+f"(c[3])
        : "r"(a[0]), "r"(a[1]), "r"(a[2]), "r"(a[3]), "r"(b0), "r"(b1));
}

__device__ __forceinline__ void ldsm4(uint32_t* r, uint32_t addr) {
    asm volatile("ldmatrix.sync.aligned.m8n8.x4.shared.b16 {%0,%1,%2,%3}, [%4];"
                 : "=r"(r[0]), "=r"(r[1]), "=r"(r[2]), "=r"(r[3]) : "r"(addr));
}

__device__ __forceinline__ uint32_t smaddr(const void* p) {
    return (uint32_t)__cvta_generic_to_shared(p);
}

__device__ __forceinline__ void red_add_v4(float* p, float a, float b, float c, float d) {
    asm volatile("red.global.add.v4.f32 [%0], {%1,%2,%3,%4};"
                 :: "l"(p), "f"(a), "f"(b), "f"(c), "f"(d) : "memory");
}

#define SK 20    // smem stride words (16 kpairs + 4 pad); LDSM-conflict-free

// fp16x2 chunk: D += Ah*Bh + Al*Bh   (B residual dropped; 32 MMA, 8 LDSM / k16)
__device__ __forceinline__ void mma_chunk_f16(
    uint32_t aH0, uint32_t aH1, uint32_t aL0, uint32_t aL1,
    uint32_t bH0, uint32_t bH1, float acc[2][4][4]) {
#pragma unroll
    for (int kc = 0; kc < 2; kc++) {
        const uint32_t kb = kc * 32;
        uint32_t a0[4], a1[4], b0[4], b1[4];
        ldsm4(a0, aH0 + kb); ldsm4(a1, aH1 + kb);
        ldsm4(b0, bH0 + kb); ldsm4(b1, bH1 + kb);
        mma4h(acc[0][0], a0, b0[0], b0[2]); mma4h(acc[0][1], a0, b0[1], b0[3]);
        mma4h(acc[0][2], a0, b1[0], b1[2]); mma4h(acc[0][3], a0, b1[1], b1[3]);
        mma4h(acc[1][0], a1, b0[0], b0[2]); mma4h(acc[1][1], a1, b0[1], b0[3]);
        mma4h(acc[1][2], a1, b1[0], b1[2]); mma4h(acc[1][3], a1, b1[1], b1[3]);
        uint32_t d0[4], d1[4];
        ldsm4(d0, aL0 + kb); ldsm4(d1, aL1 + kb);
        mma4h(acc[0][0], d0, b0[0], b0[2]); mma4h(acc[0][1], d0, b0[1], b0[3]);
        mma4h(acc[0][2], d0, b1[0], b1[2]); mma4h(acc[0][3], d0, b1[1], b1[3]);
        mma4h(acc[1][0], d1, b0[0], b0[2]); mma4h(acc[1][1], d1, b0[1], b0[3]);
        mma4h(acc[1][2], d1, b1[0], b1[2]); mma4h(acc[1][3], d1, b1[1], b1[3]);
    }
}

// bf16x3 chunk (proven; node kernels)
__device__ __forceinline__ void mma_chunk_ldsm(
    uint32_t aH0, uint32_t aH1, uint32_t aL0, uint32_t aL1,
    uint32_t bH0, uint32_t bH1, uint32_t bL0, uint32_t bL1,
    float acc[2][4][4]) {
#pragma unroll
    for (int kc = 0; kc < 2; kc++) {
        const uint32_t kb = kc * 32;
        uint32_t a0[4], a1[4], b0[4], b1[4];
        ldsm4(a0, aH0 + kb); ldsm4(a1, aH1 + kb);
        ldsm4(b0, bH0 + kb); ldsm4(b1, bH1 + kb);
        mma4(acc[0][0], a0, b0[0], b0[2]); mma4(acc[0][1], a0, b0[1], b0[3]);
        mma4(acc[0][2], a0, b1[0], b1[2]); mma4(acc[0][3], a0, b1[1], b1[3]);
        mma4(acc[1][0], a1, b0[0], b0[2]); mma4(acc[1][1], a1, b0[1], b0[3]);
        mma4(acc[1][2], a1, b1[0], b1[2]); mma4(acc[1][3], a1, b1[1], b1[3]);
        uint32_t c0[4], c1[4];
        ldsm4(c0, bL0 + kb); ldsm4(c1, bL1 + kb);
        mma4(acc[0][0], a0, c0[0], c0[2]); mma4(acc[0][1], a0, c0[1], c0[3]);
        mma4(acc[0][2], a0, c1[0], c1[2]); mma4(acc[0][3], a0, c1[1], c1[3]);
        mma4(acc[1][0], a1, c0[0], c0[2]); mma4(acc[1][1], a1, c0[1], c0[3]);
        mma4(acc[1][2], a1, c1[0], c1[2]); mma4(acc[1][3], a1, c1[1], c1[3]);
        uint32_t d0[4], d1[4];
        ldsm4(d0, aL0 + kb); ldsm4(d1, aL1 + kb);
        mma4(acc[0][0], d0, b0[0], b0[2]); mma4(acc[0][1], d0, b0[1], b0[3]);
        mma4(acc[0][2], d0, b1[0], b1[2]); mma4(acc[0][3], d0, b1[1], b1[3]);
        mma4(acc[1][0], d1, b0[0], b0[2]); mma4(acc[1][1], d1, b0[1], b0[3]);
        mma4(acc[1][2], d1, b1[0], b1[2]); mma4(acc[1][3], d1, b1[1], b1[3]);
    }
}

// ---------------- merged prep ------------------------------------------------
__global__ void prep_kernel(const float* __restrict__ W1a,
                            const float* __restrict__ W2a,
                            const float* __restrict__ W1b,
                            const float* __restrict__ W2b) {
    int i = blockIdx.x * blockDim.x + threadIdx.x;
    const float4 z = {0.f, 0.f, 0.f, 0.f};
    if (i < NNODES * H / 4) ((float4*)g_agg)[i] = z;
    if (i < H / 4) { ((float4*)g_sum)[i] = z; ((float4*)g_sumsq)[i] = z; }
    if (i < 8192) {                       // W1a -> fp16 hi
        int n = i >> 6, kp = i & 63;
        g_W1T_hi[i] = packh(W1a[(2 * kp) * 128 + n], W1a[(2 * kp + 1) * 128 + n]);
    } else if (i < 16384) {               // W2a -> fp16 hi
        int j = i - 8192, n = j >> 6, kp = j & 63;
        g_W2T_hi[j] = packh(W2a[(2 * kp) * 128 + n], W2a[(2 * kp + 1) * 128 + n]);
    } else if (i < 28672) {               // W1b -> bf16 hi/lo
        int j = i - 16384, n = j / 96, kp = j - n * 96;
        uint32_t h, l;
        split2(W1b[(2 * kp) * 128 + n], W1b[(2 * kp + 1) * 128 + n], h, l);
        g_W3T_hi[j] = h; g_W3T_lo[j] = l;
    } else if (i < 32768) {               // W2b -> bf16 hi/lo
        int j = i - 28672, n = j >> 6, kp = j & 63;
        uint32_t h, l;
        split2(W2b[(2 * kp) * OUTD + n], W2b[(2 * kp + 1) * OUTD + n], h, l);
        g_W4T_hi[j] = h; g_W4T_lo[j] = l;
    }
}

__global__ void finalize_bn(const float* __restrict__ gamma,
                            const float* __restrict__ beta, float invM) {
    int c = threadIdx.x;
    float mean = g_sum[c] * invM;
    float var  = g_sumsq[c] * invM - mean * mean;
    float sc   = gamma[c] * rsqrtf(var + BN_EPS);
    g_scale[c] = sc;
    g_shift[c] = beta[c] - mean * sc;
    g_sum[c] = 0.f; g_sumsq[c] = 0.f;
}

// ============================================================================
// Edge GEMM1 (fp16x2): h1 = concat(x[row], ea) @ W1a + b1a ; fused BN stats.
// ============================================================================
__global__ __launch_bounds__(512, 1) void edge_mma1(
    const float* __restrict__ x, const int* __restrict__ ei,
    const float* __restrict__ ea, const float* __restrict__ bias) {
    __shared__ uint32_t sAh[128 * SK], sAl[128 * SK];
    __shared__ uint32_t sBh[128 * SK];
    __shared__ int rowidx[128];
    __shared__ float s_bias[128];
    __shared__ float red_s[4][128], red_q[4][128];

    const int t = threadIdx.x, tile = blockIdx.x;
    if (t < 128) { rowidx[t] = ei[tile * 128 + t]; s_bias[t] = bias[t]; }
    __syncthreads();

    const int warp = t >> 5, lane = t & 31, g = lane >> 2, t4 = lane & 3;
    const int wm = (warp >> 2) * 32, wn = (warp & 3) * 32;
    const int m = t >> 2, q = t & 3;
    const int n = t >> 2, qb = t & 3;

    const int rA = (lane & 7) + ((lane >> 3) & 1) * 8;
    const int cH = (lane >> 4) * 4;
    const uint32_t aH0 = smaddr(&sAh[(wm + rA) * SK + cH]);
    const uint32_t aH1 = smaddr(&sAh[(wm + 16 + rA) * SK + cH]);
    const uint32_t aL0 = smaddr(&sAl[(wm + rA) * SK + cH]);
    const uint32_t aL1 = smaddr(&sAl[(wm + 16 + rA) * SK + cH]);
    const int rB = lane & 15;
    const uint32_t bH0 = smaddr(&sBh[(wn + rB) * SK + cH]);
    const uint32_t bH1 = smaddr(&sBh[(wn + 16 + rB) * SK + cH]);

    float acc[2][4][4];
#pragma unroll
    for (int i = 0; i < 2; i++)
#pragma unroll
        for (int j = 0; j < 4; j++)
#pragma unroll
            for (int k = 0; k < 4; k++) acc[i][j][k] = 0.f;

    float4 va0, va1;
    uint4 qh;
    {
        const float* src = x + (size_t)rowidx[m] * ND + q * 8;
        va0 = ((const float4*)src)[0]; va1 = ((const float4*)src)[1];
        qh = *(const uint4*)&g_W1T_hi[n * 64 + qb * 4];
    }

#pragma unroll
    for (int s = 0; s < 4; s++) {
        {
            uint32_t h0, l0, h1, l1, h2, l2, h3, l3;
            split2h(va0.x, va0.y, h0, l0); split2h(va0.z, va0.w, h1, l1);
            split2h(va1.x, va1.y, h2, l2); split2h(va1.z, va1.w, h3, l3);
            *(uint4*)&sAh[m * SK + q * 4] = make_uint4(h0, h1, h2, h3);
            *(uint4*)&sAl[m * SK + q * 4] = make_uint4(l0, l1, l2, l3);
        }
        *(uint4*)&sBh[n * SK + qb * 4] = qh;
        __syncthreads();
        if (s < 3) {
            int kb = (s + 1) * 32 + q * 8;
            const float* src = (s + 1 < 2)
                ? (x + (size_t)rowidx[m] * ND + kb)
                : (ea + (size_t)(tile * 128 + m) * ND + (kb - 64));
            va0 = ((const float4*)src)[0]; va1 = ((const float4*)src)[1];
            qh = *(const uint4*)&g_W1T_hi[n * 64 + (s + 1) * 16 + qb * 4];
        }
        mma_chunk_f16(aH0, aH1, aL0, aL1, bH0, bH1, acc);
        __syncthreads();
    }

    float s8[8] = {0, 0, 0, 0, 0, 0, 0, 0}, q8[8] = {0, 0, 0, 0, 0, 0, 0, 0};
    const int odd = t4 & 1;
#pragma unroll
    for (int mt = 0; mt < 2; mt++) {
        int r0 = wm + mt * 16 + g;
#pragma unroll
        for (int nt = 0; nt < 4; nt++) {
            int c = wn + nt * 8 + 2 * t4;
            float bx = s_bias[c], by = s_bias[c + 1];
            float v00 = acc[mt][nt][0] + bx, v01 = acc[mt][nt][1] + by;
            float v10 = acc[mt][nt][2] + bx, v11 = acc[mt][nt][3] + by;
            s8[nt * 2]     += v00 + v10;
            s8[nt * 2 + 1] += v01 + v11;
            q8[nt * 2]     += v00 * v00 + v10 * v10;
            q8[nt * 2 + 1] += v01 * v01 + v11 * v11;
            float e0 = odd ? v00 : v10;
            float e1 = odd ? v01 : v11;
            float p0 = __shfl_xor_sync(0xffffffffu, e0, 1);
            float p1 = __shfl_xor_sync(0xffffffffu, e1, 1);
            int row = r0 + odd * 8;
            int cb  = wn + nt * 8 + (t4 & 2) * 2;
            float4 quad = odd ? make_float4(p0, p1, v10, v11)
                              : make_float4(v00, v01, p0, p1);
            *(float4*)&g_h1[(size_t)(tile * 128 + row) * H + cb] = quad;
        }
    }
#pragma unroll
    for (int j = 0; j < 8; j++)
#pragma unroll
        for (int o = 4; o < 32; o <<= 1) {
            s8[j] += __shfl_xor_sync(0xffffffffu, s8[j], o);
            q8[j] += __shfl_xor_sync(0xffffffffu, q8[j], o);
        }
    if (lane < 4) {
        int wr = warp >> 2;
#pragma unroll
        for (int nt = 0; nt < 4; nt++) {
            red_s[wr][wn + nt * 8 + 2 * lane]     = s8[nt * 2];
            red_s[wr][wn + nt * 8 + 2 * lane + 1] = s8[nt * 2 + 1];
            red_q[wr][wn + nt * 8 + 2 * lane]     = q8[nt * 2];
            red_q[wr][wn + nt * 8 + 2 * lane + 1] = q8[nt * 2 + 1];
        }
    }
    __syncthreads();
    if (t < 128) {
        atomicAdd(&g_sum[t],   red_s[0][t] + red_s[1][t] + red_s[2][t] + red_s[3][t]);
        atomicAdd(&g_sumsq[t], red_q[0][t] + red_q[1][t] + red_q[2][t] + red_q[3][t]);
    }
}

// ============================================================================
// Edge GEMM2 (fp16x2) + scatter: agg[col] += relu(BN(h1)) @ W2a + b2a
// ============================================================================
__global__ __launch_bounds__(512, 1) void edge_mma2(
    const int* __restrict__ ei, const float* __restrict__ bias) {
    __shared__ uint32_t sAh[128 * SK], sAl[128 * SK];
    __shared__ uint32_t sBh[128 * SK];
    __shared__ int colidx[128];
    __shared__ float s_bias[128], s_sc[128], s_sh[128];

    const int t = threadIdx.x, tile = blockIdx.x;
    if (t < 128) {
        colidx[t] = ei[NEDGES + tile * 128 + t];
        s_bias[t] = bias[t];
        s_sc[t] = g_scale[t];
        s_sh[t] = g_shift[t];
    }
    __syncthreads();

    const int warp = t >> 5, lane = t & 31, g = lane >> 2, t4 = lane & 3;
    const int wm = (warp >> 2) * 32, wn = (warp & 3) * 32;
    const int m = t >> 2, q = t & 3;
    const int n = t >> 2, qb = t & 3;

    const int rA = (lane & 7) + ((lane >> 3) & 1) * 8;
    const int cH = (lane >> 4) * 4;
    const uint32_t aH0 = smaddr(&sAh[(wm + rA) * SK + cH]);
    const uint32_t aH1 = smaddr(&sAh[(wm + 16 + rA) * SK + cH]);
    const uint32_t aL0 = smaddr(&sAl[(wm + rA) * SK + cH]);
    const uint32_t aL1 = smaddr(&sAl[(wm + 16 + rA) * SK + cH]);
    const int rB = lane & 15;
    const uint32_t bH0 = smaddr(&sBh[(wn + rB) * SK + cH]);
    const uint32_t bH1 = smaddr(&sBh[(wn + 16 + rB) * SK + cH]);

    float acc[2][4][4];
#pragma unroll
    for (int i = 0; i < 2; i++)
#pragma unroll
        for (int j = 0; j < 4; j++)
#pragma unroll
            for (int k = 0; k < 4; k++) acc[i][j][k] = 0.f;

    float4 va0, va1;
    uint4 qh;
    {
        const float* src = g_h1 + (size_t)(tile * 128 + m) * H + q * 8;
        va0 = ((const float4*)src)[0]; va1 = ((const float4*)src)[1];
        qh = *(const uint4*)&g_W2T_hi[n * 64 + qb * 4];
    }

#pragma unroll
    for (int s = 0; s < 4; s++) {
        {
            int kb = s * 32 + q * 8;
            float4 v0 = va0, v1 = va1;
            v0.x = fmaxf(fmaf(v0.x, s_sc[kb],     s_sh[kb]),     0.f);
            v0.y = fmaxf(fmaf(v0.y, s_sc[kb + 1], s_sh[kb + 1]), 0.f);
            v0.z = fmaxf(fmaf(v0.z, s_sc[kb + 2], s_sh[kb + 2]), 0.f);
            v0.w = fmaxf(fmaf(v0.w, s_sc[kb + 3], s_sh[kb + 3]), 0.f);
            v1.x = fmaxf(fmaf(v1.x, s_sc[kb + 4], s_sh[kb + 4]), 0.f);
            v1.y = fmaxf(fmaf(v1.y, s_sc[kb + 5], s_sh[kb + 5]), 0.f);
            v1.z = fmaxf(fmaf(v1.z, s_sc[kb + 6], s_sh[kb + 6]), 0.f);
            v1.w = fmaxf(fmaf(v1.w, s_sc[kb + 7], s_sh[kb + 7]), 0.f);
            uint32_t h0, l0, h1, l1, h2, l2, h3, l3;
            split2h(v0.x, v0.y, h0, l0); split2h(v0.z, v0.w, h1, l1);
            split2h(v1.x, v1.y, h2, l2); split2h(v1.z, v1.w, h3, l3);
            *(uint4*)&sAh[m * SK + q * 4] = make_uint4(h0, h1, h2, h3);
            *(uint4*)&sAl[m * SK + q * 4] = make_uint4(l0, l1, l2, l3);
        }
        *(uint4*)&sBh[n * SK + qb * 4] = qh;
        __syncthreads();
        if (s < 3) {
            const float* src = g_h1 + (size_t)(tile * 128 + m) * H + (s + 1) * 32 + q * 8;
            va0 = ((const float4*)src)[0]; va1 = ((const float4*)src)[1];
            qh = *(const uint4*)&g_W2T_hi[n * 64 + (s + 1) * 16 + qb * 4];
        }
        mma_chunk_f16(aH0, aH1, aL0, aL1, bH0, bH1, acc);
        __syncthreads();
    }

    const int odd = t4 & 1;
#pragma unroll
    for (int mt = 0; mt < 2; mt++) {
        int r0 = wm + mt * 16 + g;
#pragma unroll
        for (int nt = 0; nt < 4; nt++) {
            int c = wn + nt * 8 + 2 * t4;
            float bx = s_bias[c], by = s_bias[c + 1];
            float v00 = acc[mt][nt][0] + bx, v01 = acc[mt][nt][1] + by;
            float v10 = acc[mt][nt][2] + bx, v11 = acc[mt][nt][3] + by;
            float e0 = odd ? v00 : v10;
            float e1 = odd ? v01 : v11;
            float p0 = __shfl_xor_sync(0xffffffffu, e0, 1);
            float p1 = __shfl_xor_sync(0xffffffffu, e1, 1);
            int row = r0 + odd * 8;
            int node = colidx[row];
            int cb  = wn + nt * 8 + (t4 & 2) * 2;
            if (odd)
                red_add_v4(&g_agg[(size_t)node * H + cb], p0, p1, v10, v11);
            else
                red_add_v4(&g_agg[(size_t)node * H + cb], v00, v01, p0, p1);
        }
    }
}

// ============================================================================
// Node MMA1 (bf16x3, round-13 proven, verbatim)
// ============================================================================
__global__ __launch_bounds__(512, 1) void node_mma1(
    const float* __restrict__ x, const float* __restrict__ bias) {
    __shared__ uint32_t sAh[128 * SK], sAl[128 * SK];
    __shared__ uint32_t sBh[128 * SK], sBl[128 * SK];
    __shared__ float s_bias[128];
    __shared__ float red_s[4][128], red_q[4][128];

    const int t = threadIdx.x, tile = blockIdx.x;
    if (t < 128) s_bias[t] = bias[t];
    __syncthreads();

    const int warp = t >> 5, lane = t & 31, g = lane >> 2, t4 = lane & 3;
    const int wm = (warp >> 2) * 32, wn = (warp & 3) * 32;
    const int m = t >> 2, q = t & 3;
    const int n = t >> 2, qb = t & 3;
    const int grow = tile * 128 + m;
    const bool rok = grow < NNODES;

    const int rA = (lane & 7) + ((lane >> 3) & 1) * 8;
    const int cH = (lane >> 4) * 4;
    const uint32_t aH0 = smaddr(&sAh[(wm + rA) * SK + cH]);
    const uint32_t aH1 = smaddr(&sAh[(wm + 16 + rA) * SK + cH]);
    const uint32_t aL0 = smaddr(&sAl[(wm + rA) * SK + cH]);
    const uint32_t aL1 = smaddr(&sAl[(wm + 16 + rA) * SK + cH]);
    const int rB = lane & 15;
    const uint32_t bH0 = smaddr(&sBh[(wn + rB) * SK + cH]);
    const uint32_t bH1 = smaddr(&sBh[(wn + 16 + rB) * SK + cH]);
    const uint32_t bL0 = smaddr(&sBl[(wn + rB) * SK + cH]);
    const uint32_t bL1 = smaddr(&sBl[(wn + 16 + rB) * SK + cH]);

    float acc[2][4][4];
#pragma unroll
    for (int i = 0; i < 2; i++)
#pragma unroll
        for (int j = 0; j < 4; j++)
#pragma unroll
            for (int k = 0; k < 4; k++) acc[i][j][k] = 0.f;

    auto loadA = [&](int s, float4& v0, float4& v1) {
        if (!rok) { v0 = make_float4(0, 0, 0, 0); v1 = v0; return; }
        int k = s * 32 + q * 8;
        const float* src = (s < 2) ? (x + (size_t)grow * ND + k)
                                   : (g_agg + (size_t)grow * H + (k - 64));
        v0 = ((const float4*)src)[0]; v1 = ((const float4*)src)[1];
    };

    float4 va0, va1;
    uint4 qh, ql;
    loadA(0, va0, va1);
    qh = *(const uint4*)&g_W3T_hi[n * 96 + qb * 4];
    ql = *(const uint4*)&g_W3T_lo[n * 96 + qb * 4];

#pragma unroll
    for (int s = 0; s < 6; s++) {
        {
            uint32_t h0, l0, h1, l1, h2, l2, h3, l3;
            split2(va0.x, va0.y, h0, l0); split2(va0.z, va0.w, h1, l1);
            split2(va1.x, va1.y, h2, l2); split2(va1.z, va1.w, h3, l3);
            *(uint4*)&sAh[m * SK + q * 4] = make_uint4(h0, h1, h2, h3);
            *(uint4*)&sAl[m * SK + q * 4] = make_uint4(l0, l1, l2, l3);
        }
        {
            *(uint4*)&sBh[n * SK + qb * 4] = qh;
            *(uint4*)&sBl[n * SK + qb * 4] = ql;
        }
        __syncthreads();
        if (s < 5) {
            loadA(s + 1, va0, va1);
            qh = *(const uint4*)&g_W3T_hi[n * 96 + (s + 1) * 16 + qb * 4];
            ql = *(const uint4*)&g_W3T_lo[n * 96 + (s + 1) * 16 + qb * 4];
        }
        mma_chunk_ldsm(aH0, aH1, aL0, aL1, bH0, bH1, bL0, bL1, acc);
        __syncthreads();
    }

    float s8[8] = {0, 0, 0, 0, 0, 0, 0, 0}, q8[8] = {0, 0, 0, 0, 0, 0, 0, 0};
#pragma unroll
    for (int mt = 0; mt < 2; mt++) {
        int r0 = wm + mt * 16 + g;
        int n0 = tile * 128 + r0, n1 = n0 + 8;
        bool ok0 = n0 < NNODES, ok1 = n1 < NNODES;
#pragma unroll
        for (int nt = 0; nt < 4; nt++) {
            int c = wn + nt * 8 + 2 * t4;
            float bx = s_bias[c], by = s_bias[c + 1];
            float v00 = acc[mt][nt][0] + bx, v01 = acc[mt][nt][1] + by;
            float v10 = acc[mt][nt][2] + bx, v11 = acc[mt][nt][3] + by;
            if (ok0) {
                float2 w0 = {v00, v01};
                *(float2*)&g_h2[(size_t)n0 * H + c] = w0;
                s8[nt * 2] += v00; s8[nt * 2 + 1] += v01;
                q8[nt * 2] += v00 * v00; q8[nt * 2 + 1] += v01 * v01;
            }
            if (ok1) {
                float2 w1 = {v10, v11};
                *(float2*)&g_h2[(size_t)n1 * H + c] = w1;
                s8[nt * 2] += v10; s8[nt * 2 + 1] += v11;
                q8[nt * 2] += v10 * v10; q8[nt * 2 + 1] += v11 * v11;
            }
        }
    }
#pragma unroll
    for (int j = 0; j < 8; j++)
#pragma unroll
        for (int o = 4; o < 32; o <<= 1) {
            s8[j] += __shfl_xor_sync(0xffffffffu, s8[j], o);
            q8[j] += __shfl_xor_sync(0xffffffffu, q8[j], o);
        }
    if (lane < 4) {
        int wr = warp >> 2;
#pragma unroll
        for (int nt = 0; nt < 4; nt++) {
            red_s[wr][wn + nt * 8 + 2 * lane]     = s8[nt * 2];
            red_s[wr][wn + nt * 8 + 2 * lane + 1] = s8[nt * 2 + 1];
            red_q[wr][wn + nt * 8 + 2 * lane]     = q8[nt * 2];
            red_q[wr][wn + nt * 8 + 2 * lane + 1] = q8[nt * 2 + 1];
        }
    }
    __syncthreads();
    if (t < 128) {
        atomicAdd(&g_sum[t],   red_s[0][t] + red_s[1][t] + red_s[2][t] + red_s[3][t]);
        atomicAdd(&g_sumsq[t], red_q[0][t] + red_q[1][t] + red_q[2][t] + red_q[3][t]);
    }
}

// ============================================================================
// Node MMA2 (bf16x3, round-13 proven, verbatim)
// ============================================================================
__global__ __launch_bounds__(256, 2) void node_mma2(
    const float* __restrict__ bias, float* __restrict__ out) {
    __shared__ uint32_t sAh[128 * SK], sAl[128 * SK];
    __shared__ uint32_t sBh[64 * SK], sBl[64 * SK];
    __shared__ float s_bias[64], s_sc[128], s_sh[128];

    const int t = threadIdx.x, tile = blockIdx.x;
    if (t < 64) s_bias[t] = bias[t];
    if (t < 128) { s_sc[t] = g_scale[t]; s_sh[t] = g_shift[t]; }
    __syncthreads();

    const int warp = t >> 5, lane = t & 31, g = lane >> 2, t4 = lane & 3;
    const int wm = (warp >> 1) * 32, wn = (warp & 1) * 32;
    const int m = t >> 1, q2 = t & 1;
    const int n = t >> 2, qb = t & 3;
    const int grow = tile * 128 + m;
    const bool rok = grow < NNODES;

    const int rA = (lane & 7) + ((lane >> 3) & 1) * 8;
    const int cH = (lane >> 4) * 4;
    const uint32_t aH0 = smaddr(&sAh[(wm + rA) * SK + cH]);
    const uint32_t aH1 = smaddr(&sAh[(wm + 16 + rA) * SK + cH]);
    const uint32_t aL0 = smaddr(&sAl[(wm + rA) * SK + cH]);
    const uint32_t aL1 = smaddr(&sAl[(wm + 16 + rA) * SK + cH]);
    const int rB = lane & 15;
    const uint32_t bH0 = smaddr(&sBh[(wn + rB) * SK + cH]);
    const uint32_t bH1 = smaddr(&sBh[(wn + 16 + rB) * SK + cH]);
    const uint32_t bL0 = smaddr(&sBl[(wn + rB) * SK + cH]);
    const uint32_t bL1 = smaddr(&sBl[(wn + 16 + rB) * SK + cH]);

    float acc[2][4][4];
#pragma unroll
    for (int i = 0; i < 2; i++)
#pragma unroll
        for (int j = 0; j < 4; j++)
#pragma unroll
            for (int k = 0; k < 4; k++) acc[i][j][k] = 0.f;

    float4 va0, va1, va2, va3;
    uint4 qh, ql;
    auto loadA = [&](int s) {
        if (!rok) { va0 = make_float4(0, 0, 0, 0); va1 = va0; va2 = va0; va3 = va0; return; }
        const float* src = g_h2 + (size_t)grow * H + s * 32 + q2 * 16;
        va0 = ((const float4*)src)[0]; va1 = ((const float4*)src)[1];
        va2 = ((const float4*)src)[2]; va3 = ((const float4*)src)[3];
    };
    auto storeA = [&](int s) {
        int kb = s * 32 + q2 * 16;
        float4 v[4] = {va0, va1, va2, va3};
#pragma unroll
        for (int j = 0; j < 4; j++) {
            int k = kb + 4 * j;
            v[j].x = fmaxf(fmaf(v[j].x, s_sc[k],     s_sh[k]),     0.f);
            v[j].y = fmaxf(fmaf(v[j].y, s_sc[k + 1], s_sh[k + 1]), 0.f);
            v[j].z = fmaxf(fmaf(v[j].z, s_sc[k + 2], s_sh[k + 2]), 0.f);
            v[j].w = fmaxf(fmaf(v[j].w, s_sc[k + 3], s_sh[k + 3]), 0.f);
        }
        uint32_t h[8], l[8];
#pragma unroll
        for (int j = 0; j < 4; j++) {
            split2(v[j].x, v[j].y, h[2 * j], l[2 * j]);
            split2(v[j].z, v[j].w, h[2 * j + 1], l[2 * j + 1]);
        }
        *(uint4*)&sAh[m * SK + q2 * 8]     = make_uint4(h[0], h[1], h[2], h[3]);
        *(uint4*)&sAh[m * SK + q2 * 8 + 4] = make_uint4(h[4], h[5], h[6], h[7]);
        *(uint4*)&sAl[m * SK + q2 * 8]     = make_uint4(l[0], l[1], l[2], l[3]);
        *(uint4*)&sAl[m * SK + q2 * 8 + 4] = make_uint4(l[4], l[5], l[6], l[7]);
    };

    loadA(0);
    qh = *(const uint4*)&g_W4T_hi[n * 64 + qb * 4];
    ql = *(const uint4*)&g_W4T_lo[n * 64 + qb * 4];

#pragma unroll
    for (int s = 0; s < 4; s++) {
        storeA(s);
        *(uint4*)&sBh[n * SK + qb * 4] = qh;
        *(uint4*)&sBl[n * SK + qb * 4] = ql;
        __syncthreads();
        if (s < 3) {
            loadA(s + 1);
            qh = *(const uint4*)&g_W4T_hi[n * 64 + (s + 1) * 16 + qb * 4];
            ql = *(const uint4*)&g_W4T_lo[n * 64 + (s + 1) * 16 + qb * 4];
        }
        mma_chunk_ldsm(aH0, aH1, aL0, aL1, bH0, bH1, bL0, bL1, acc);
        __syncthreads();
    }

    const int odd = t4 & 1;
#pragma unroll
    for (int mt = 0; mt < 2; mt++) {
        int r0 = wm + mt * 16 + g;
#pragma unroll
        for (int nt = 0; nt < 4; nt++) {
            int c = wn + nt * 8 + 2 * t4;
            float bx = s_bias[c], by = s_bias[c + 1];
            float v00 = acc[mt][nt][0] + bx, v01 = acc[mt][nt][1] + by;
            float v10 = acc[mt][nt][2] + bx, v11 = acc[mt][nt][3] + by;
            float e0 = odd ? v00 : v10;
            float e1 = odd ? v01 : v11;
            float p0 = __shfl_xor_sync(0xffffffffu, e0, 1);
            float p1 = __shfl_xor_sync(0xffffffffu, e1, 1);
            int row = r0 + odd * 8;
            int gn = tile * 128 + row;
            int cb = wn + nt * 8 + (t4 & 2) * 2;
            float4 quad = odd ? make_float4(p0, p1, v10, v11)
                              : make_float4(v00, v01, p0, p1);
            if (gn < NNODES)
                *(float4*)&out[(size_t)gn * OUTD + cb] = quad;
        }
    }
}

// ============================================================================
extern "C" void kernel_launch(void* const* d_in, const int* in_sizes, int n_in,
                              void* d_out, int out_size) {
    const float* x    = (const float*)d_in[0];
    const int*   ei   = (const int*)d_in[1];
    const float* ea   = (const float*)d_in[2];
    const float* W1a  = (const float*)d_in[5];
    const float* b1a  = (const float*)d_in[6];
    const float* g1a  = (const float*)d_in[7];
    const float* be1a = (const float*)d_in[8];
    const float* W2a  = (const float*)d_in[9];
    const float* b2a  = (const float*)d_in[10];
    const float* W1b  = (const float*)d_in[11];
    const float* b1b  = (const float*)d_in[12];
    const float* g1b  = (const float*)d_in[13];
    const float* be1b = (const float*)d_in[14];
    const float* W2b  = (const float*)d_in[15];
    const float* b2b  = (const float*)d_in[16];
    float* out = (float*)d_out;

    prep_kernel<<<(NNODES * H / 4 + 255) / 256, 256>>>(W1a, W2a, W1b, W2b);
    edge_mma1<<<NTILES2, 512>>>(x, ei, ea, b1a);
    finalize_bn<<<1, 128>>>(g1a, be1a, 1.0f / (float)NEDGES);
    edge_mma2<<<NTILES2, 512>>>(ei, b2a);
    node_mma1<<<NODE_TILES, 512>>>(x, b1b);
    finalize_bn<<<1, 128>>>(g1b, be1b, 1.0f / (float)NNODES);
    node_mma2<<<NODE_TILES, 256>>>(b2b, out);
}

// round 17
// speedup vs baseline: 1.3270x; 1.1547x over previous
#include <cuda_runtime.h>
#include <cuda_bf16.h>
#include <cuda_fp16.h>
#include <cstdint>

#define NNODES 50000
#define NEDGES 800000
#define ND     64
#define H      128
#define OUTD   64
#define BN_EPS 1e-5f
#define NTILES2 (NEDGES / 128)             // 6250
#define NODE_TILES ((NNODES + 127) / 128)  // 391

// ---------------- scratch (device globals; no allocations allowed) ----------
__device__ float g_h1[(size_t)NEDGES * H];
__device__ float g_agg[(size_t)NNODES * H];
__device__ float g_h2[(size_t)NNODES * H];
__device__ float g_sum[H];
__device__ float g_sumsq[H];
__device__ float g_scale[H];
__device__ float g_shift[H];
// edge weights: fp16, word(n,kpair) = f16{k}|f16{k+1}<<16
__device__ __align__(16) uint32_t g_W1T_hi[128 * 64];
__device__ __align__(16) uint32_t g_W2T_hi[128 * 64];
// node weights: bf16 hi/lo (bf16x3 scheme)
__device__ __align__(16) uint32_t g_W3T_hi[128 * 96];
__device__ __align__(16) uint32_t g_W3T_lo[128 * 96];
__device__ __align__(16) uint32_t g_W4T_hi[64 * 64];
__device__ __align__(16) uint32_t g_W4T_lo[64 * 64];

// ---------------- helpers ----------------------------------------------------
__device__ __forceinline__ void split2(float a, float b, uint32_t& hi, uint32_t& lo) {
    __nv_bfloat16 ah = __float2bfloat16_rn(a), bh = __float2bfloat16_rn(b);
    float ar = a - __bfloat162float(ah);
    float br = b - __bfloat162float(bh);
    __nv_bfloat16 al = __float2bfloat16_rn(ar), bl = __float2bfloat16_rn(br);
    hi = (uint32_t)__bfloat16_as_ushort(ah) | ((uint32_t)__bfloat16_as_ushort(bh) << 16);
    lo = (uint32_t)__bfloat16_as_ushort(al) | ((uint32_t)__bfloat16_as_ushort(bl) << 16);
}

__device__ __forceinline__ uint32_t packh(float a, float b) {
    __half ah = __float2half_rn(a), bh = __float2half_rn(b);
    return (uint32_t)__half_as_ushort(ah) | ((uint32_t)__half_as_ushort(bh) << 16);
}

__device__ __forceinline__ void mma4(float* c, const uint32_t* a, uint32_t b0, uint32_t b1) {
    asm volatile(
        "mma.sync.aligned.m16n8k16.row.col.f32.bf16.bf16.f32 "
        "{%0,%1,%2,%3}, {%4,%5,%6,%7}, {%8,%9}, {%0,%1,%2,%3};"
        : "+f"(c[0]), "+f"(c[1]), "+f"(c[2]), "+f"(c[3])
        : "r"(a[0]), "r"(a[1]), "r"(a[2]), "r"(a[3]), "r"(b0), "r"(b1));
}
__device__ __forceinline__ void mma4h(float* c, const uint32_t* a, uint32_t b0, uint32_t b1) {
    asm volatile(
        "mma.sync.aligned.m16n8k16.row.col.f32.f16.f16.f32 "
        "{%0,%1,%2,%3}, {%4,%5,%6,%7}, {%8,%9}, {%0,%1,%2,%3};"
        : "+f"(c[0]), "+f"(c[1]), "+f"(c[2]), "+f"(c[3])
        : "r"(a[0]), "r"(a[1]), "r"(a[2]), "r"(a[3]), "r"(b0), "r"(b1));
}

__device__ __forceinline__ void ldsm4(uint32_t* r, uint32_t addr) {
    asm volatile("ldmatrix.sync.aligned.m8n8.x4.shared.b16 {%0,%1,%2,%3}, [%4];"
                 : "=r"(r[0]), "=r"(r[1]), "=r"(r[2]), "=r"(r[3]) : "r"(addr));
}

__device__ __forceinline__ uint32_t smaddr(const void* p) {
    return (uint32_t)__cvta_generic_to_shared(p);
}

__device__ __forceinline__ void red_add_v4(float* p, float a, float b, float c, float d) {
    asm volatile("red.global.add.v4.f32 [%0], {%1,%2,%3,%4};"
                 :: "l"(p), "f"(a), "f"(b), "f"(c), "f"(d) : "memory");
}

#define SK 20    // smem stride words (16 kpairs + 4 pad); LDSM-conflict-free

// pure-fp16 chunk: D += Ah*Bh   (16 MMA, 4 LDSM per k16)
__device__ __forceinline__ void mma_chunk_f16s(
    uint32_t aH0, uint32_t aH1, uint32_t bH0, uint32_t bH1,
    float acc[2][4][4]) {
#pragma unroll
    for (int kc = 0; kc < 2; kc++) {
        const uint32_t kb = kc * 32;
        uint32_t a0[4], a1[4], b0[4], b1[4];
        ldsm4(a0, aH0 + kb); ldsm4(a1, aH1 + kb);
        ldsm4(b0, bH0 + kb); ldsm4(b1, bH1 + kb);
        mma4h(acc[0][0], a0, b0[0], b0[2]); mma4h(acc[0][1], a0, b0[1], b0[3]);
        mma4h(acc[0][2], a0, b1[0], b1[2]); mma4h(acc[0][3], a0, b1[1], b1[3]);
        mma4h(acc[1][0], a1, b0[0], b0[2]); mma4h(acc[1][1], a1, b0[1], b0[3]);
        mma4h(acc[1][2], a1, b1[0], b1[2]); mma4h(acc[1][3], a1, b1[1], b1[3]);
    }
}

// bf16x3 chunk (proven; node kernels)
__device__ __forceinline__ void mma_chunk_ldsm(
    uint32_t aH0, uint32_t aH1, uint32_t aL0, uint32_t aL1,
    uint32_t bH0, uint32_t bH1, uint32_t bL0, uint32_t bL1,
    float acc[2][4][4]) {
#pragma unroll
    for (int kc = 0; kc < 2; kc++) {
        const uint32_t kb = kc * 32;
        uint32_t a0[4], a1[4], b0[4], b1[4];
        ldsm4(a0, aH0 + kb); ldsm4(a1, aH1 + kb);
        ldsm4(b0, bH0 + kb); ldsm4(b1, bH1 + kb);
        mma4(acc[0][0], a0, b0[0], b0[2]); mma4(acc[0][1], a0, b0[1], b0[3]);
        mma4(acc[0][2], a0, b1[0], b1[2]); mma4(acc[0][3], a0, b1[1], b1[3]);
        mma4(acc[1][0], a1, b0[0], b0[2]); mma4(acc[1][1], a1, b0[1], b0[3]);
        mma4(acc[1][2], a1, b1[0], b1[2]); mma4(acc[1][3], a1, b1[1], b1[3]);
        uint32_t c0[4], c1[4];
        ldsm4(c0, bL0 + kb); ldsm4(c1, bL1 + kb);
        mma4(acc[0][0], a0, c0[0], c0[2]); mma4(acc[0][1], a0, c0[1], c0[3]);
        mma4(acc[0][2], a0, c1[0], c1[2]); mma4(acc[0][3], a0, c1[1], c1[3]);
        mma4(acc[1][0], a1, c0[0], c0[2]); mma4(acc[1][1], a1, c0[1], c0[3]);
        mma4(acc[1][2], a1, c1[0], c1[2]); mma4(acc[1][3], a1, c1[1], c1[3]);
        uint32_t d0[4], d1[4];
        ldsm4(d0, aL0 + kb); ldsm4(d1, aL1 + kb);
        mma4(acc[0][0], d0, b0[0], b0[2]); mma4(acc[0][1], d0, b0[1], b0[3]);
        mma4(acc[0][2], d0, b1[0], b1[2]); mma4(acc[0][3], d0, b1[1], b1[3]);
        mma4(acc[1][0], d1, b0[0], b0[2]); mma4(acc[1][1], d1, b0[1], b0[3]);
        mma4(acc[1][2], d1, b1[0], b1[2]); mma4(acc[1][3], d1, b1[1], b1[3]);
    }
}

// ---------------- merged prep ------------------------------------------------
__global__ void prep_kernel(const float* __restrict__ W1a,
                            const float* __restrict__ W2a,
                            const float* __restrict__ W1b,
                            const float* __restrict__ W2b) {
    int i = blockIdx.x * blockDim.x + threadIdx.x;
    const float4 z = {0.f, 0.f, 0.f, 0.f};
    if (i < NNODES * H / 4) ((float4*)g_agg)[i] = z;
    if (i < H / 4) { ((float4*)g_sum)[i] = z; ((float4*)g_sumsq)[i] = z; }
    if (i < 8192) {
        int n = i >> 6, kp = i & 63;
        g_W1T_hi[i] = packh(W1a[(2 * kp) * 128 + n], W1a[(2 * kp + 1) * 128 + n]);
    } else if (i < 16384) {
        int j = i - 8192, n = j >> 6, kp = j & 63;
        g_W2T_hi[j] = packh(W2a[(2 * kp) * 128 + n], W2a[(2 * kp + 1) * 128 + n]);
    } else if (i < 28672) {
        int j = i - 16384, n = j / 96, kp = j - n * 96;
        uint32_t h, l;
        split2(W1b[(2 * kp) * 128 + n], W1b[(2 * kp + 1) * 128 + n], h, l);
        g_W3T_hi[j] = h; g_W3T_lo[j] = l;
    } else if (i < 32768) {
        int j = i - 28672, n = j >> 6, kp = j & 63;
        uint32_t h, l;
        split2(W2b[(2 * kp) * OUTD + n], W2b[(2 * kp + 1) * OUTD + n], h, l);
        g_W4T_hi[j] = h; g_W4T_lo[j] = l;
    }
}

__global__ void finalize_bn(const float* __restrict__ gamma,
                            const float* __restrict__ beta, float invM) {
    int c = threadIdx.x;
    float mean = g_sum[c] * invM;
    float var  = g_sumsq[c] * invM - mean * mean;
    float sc   = gamma[c] * rsqrtf(var + BN_EPS);
    g_scale[c] = sc;
    g_shift[c] = beta[c] - mean * sc;
    g_sum[c] = 0.f; g_sumsq[c] = 0.f;
}

// ============================================================================
// Edge GEMM1 (pure fp16): h1 = concat(x[row], ea) @ W1a + b1a ; fused BN stats.
// ============================================================================
__global__ __launch_bounds__(512, 1) void edge_mma1(
    const float* __restrict__ x, const int* __restrict__ ei,
    const float* __restrict__ ea, const float* __restrict__ bias) {
    __shared__ uint32_t sAh[128 * SK];
    __shared__ uint32_t sBh[128 * SK];
    __shared__ int rowidx[128];
    __shared__ float s_bias[128];
    __shared__ float red_s[4][128], red_q[4][128];

    const int t = threadIdx.x, tile = blockIdx.x;
    if (t < 128) { rowidx[t] = ei[tile * 128 + t]; s_bias[t] = bias[t]; }
    __syncthreads();

    const int warp = t >> 5, lane = t & 31, g = lane >> 2, t4 = lane & 3;
    const int wm = (warp >> 2) * 32, wn = (warp & 3) * 32;
    const int m = t >> 2, q = t & 3;
    const int n = t >> 2, qb = t & 3;

    const int rA = (lane & 7) + ((lane >> 3) & 1) * 8;
    const int cH = (lane >> 4) * 4;
    const uint32_t aH0 = smaddr(&sAh[(wm + rA) * SK + cH]);
    const uint32_t aH1 = smaddr(&sAh[(wm + 16 + rA) * SK + cH]);
    const int rB = lane & 15;
    const uint32_t bH0 = smaddr(&sBh[(wn + rB) * SK + cH]);
    const uint32_t bH1 = smaddr(&sBh[(wn + 16 + rB) * SK + cH]);

    float acc[2][4][4];
#pragma unroll
    for (int i = 0; i < 2; i++)
#pragma unroll
        for (int j = 0; j < 4; j++)
#pragma unroll
            for (int k = 0; k < 4; k++) acc[i][j][k] = 0.f;

    float4 va0, va1;
    uint4 qh;
    {
        const float* src = x + (size_t)rowidx[m] * ND + q * 8;
        va0 = ((const float4*)src)[0]; va1 = ((const float4*)src)[1];
        qh = *(const uint4*)&g_W1T_hi[n * 64 + qb * 4];
    }

#pragma unroll
    for (int s = 0; s < 4; s++) {
        *(uint4*)&sAh[m * SK + q * 4] = make_uint4(
            packh(va0.x, va0.y), packh(va0.z, va0.w),
            packh(va1.x, va1.y), packh(va1.z, va1.w));
        *(uint4*)&sBh[n * SK + qb * 4] = qh;
        __syncthreads();
        if (s < 3) {
            int kb = (s + 1) * 32 + q * 8;
            const float* src = (s + 1 < 2)
                ? (x + (size_t)rowidx[m] * ND + kb)
                : (ea + (size_t)(tile * 128 + m) * ND + (kb - 64));
            va0 = ((const float4*)src)[0]; va1 = ((const float4*)src)[1];
            qh = *(const uint4*)&g_W1T_hi[n * 64 + (s + 1) * 16 + qb * 4];
        }
        mma_chunk_f16s(aH0, aH1, bH0, bH1, acc);
        __syncthreads();
    }

    float s8[8] = {0, 0, 0, 0, 0, 0, 0, 0}, q8[8] = {0, 0, 0, 0, 0, 0, 0, 0};
    const int odd = t4 & 1;
#pragma unroll
    for (int mt = 0; mt < 2; mt++) {
        int r0 = wm + mt * 16 + g;
#pragma unroll
        for (int nt = 0; nt < 4; nt++) {
            int c = wn + nt * 8 + 2 * t4;
            float bx = s_bias[c], by = s_bias[c + 1];
            float v00 = acc[mt][nt][0] + bx, v01 = acc[mt][nt][1] + by;
            float v10 = acc[mt][nt][2] + bx, v11 = acc[mt][nt][3] + by;
            s8[nt * 2]     += v00 + v10;
            s8[nt * 2 + 1] += v01 + v11;
            q8[nt * 2]     += v00 * v00 + v10 * v10;
            q8[nt * 2 + 1] += v01 * v01 + v11 * v11;
            float e0 = odd ? v00 : v10;
            float e1 = odd ? v01 : v11;
            float p0 = __shfl_xor_sync(0xffffffffu, e0, 1);
            float p1 = __shfl_xor_sync(0xffffffffu, e1, 1);
            int row = r0 + odd * 8;
            int cb  = wn + nt * 8 + (t4 & 2) * 2;
            float4 quad = odd ? make_float4(p0, p1, v10, v11)
                              : make_float4(v00, v01, p0, p1);
            *(float4*)&g_h1[(size_t)(tile * 128 + row) * H + cb] = quad;
        }
    }
#pragma unroll
    for (int j = 0; j < 8; j++)
#pragma unroll
        for (int o = 4; o < 32; o <<= 1) {
            s8[j] += __shfl_xor_sync(0xffffffffu, s8[j], o);
            q8[j] += __shfl_xor_sync(0xffffffffu, q8[j], o);
        }
    if (lane < 4) {
        int wr = warp >> 2;
#pragma unroll
        for (int nt = 0; nt < 4; nt++) {
            red_s[wr][wn + nt * 8 + 2 * lane]     = s8[nt * 2];
            red_s[wr][wn + nt * 8 + 2 * lane + 1] = s8[nt * 2 + 1];
            red_q[wr][wn + nt * 8 + 2 * lane]     = q8[nt * 2];
            red_q[wr][wn + nt * 8 + 2 * lane + 1] = q8[nt * 2 + 1];
        }
    }
    __syncthreads();
    if (t < 128) {
        atomicAdd(&g_sum[t],   red_s[0][t] + red_s[1][t] + red_s[2][t] + red_s[3][t]);
        atomicAdd(&g_sumsq[t], red_q[0][t] + red_q[1][t] + red_q[2][t] + red_q[3][t]);
    }
}

// ============================================================================
// Edge GEMM2 (pure fp16) + scatter: agg[col] += relu(BN(h1)) @ W2a + b2a
// ============================================================================
__global__ __launch_bounds__(512, 1) void edge_mma2(
    const int* __restrict__ ei, const float* __restrict__ bias) {
    __shared__ uint32_t sAh[128 * SK];
    __shared__ uint32_t sBh[128 * SK];
    __shared__ int colidx[128];
    __shared__ float s_bias[128], s_sc[128], s_sh[128];

    const int t = threadIdx.x, tile = blockIdx.x;
    if (t < 128) {
        colidx[t] = ei[NEDGES + tile * 128 + t];
        s_bias[t] = bias[t];
        s_sc[t] = g_scale[t];
        s_sh[t] = g_shift[t];
    }
    __syncthreads();

    const int warp = t >> 5, lane = t & 31, g = lane >> 2, t4 = lane & 3;
    const int wm = (warp >> 2) * 32, wn = (warp & 3) * 32;
    const int m = t >> 2, q = t & 3;
    const int n = t >> 2, qb = t & 3;

    const int rA = (lane & 7) + ((lane >> 3) & 1) * 8;
    const int cH = (lane >> 4) * 4;
    const uint32_t aH0 = smaddr(&sAh[(wm + rA) * SK + cH]);
    const uint32_t aH1 = smaddr(&sAh[(wm + 16 + rA) * SK + cH]);
    const int rB = lane & 15;
    const uint32_t bH0 = smaddr(&sBh[(wn + rB) * SK + cH]);
    const uint32_t bH1 = smaddr(&sBh[(wn + 16 + rB) * SK + cH]);

    float acc[2][4][4];
#pragma unroll
    for (int i = 0; i < 2; i++)
#pragma unroll
        for (int j = 0; j < 4; j++)
#pragma unroll
            for (int k = 0; k < 4; k++) acc[i][j][k] = 0.f;

    float4 va0, va1;
    uint4 qh;
    {
        const float* src = g_h1 + (size_t)(tile * 128 + m) * H + q * 8;
        va0 = ((const float4*)src)[0]; va1 = ((const float4*)src)[1];
        qh = *(const uint4*)&g_W2T_hi[n * 64 + qb * 4];
    }

#pragma unroll
    for (int s = 0; s < 4; s++) {
        {
            int kb = s * 32 + q * 8;
            float4 v0 = va0, v1 = va1;
            v0.x = fmaxf(fmaf(v0.x, s_sc[kb],     s_sh[kb]),     0.f);
            v0.y = fmaxf(fmaf(v0.y, s_sc[kb + 1], s_sh[kb + 1]), 0.f);
            v0.z = fmaxf(fmaf(v0.z, s_sc[kb + 2], s_sh[kb + 2]), 0.f);
            v0.w = fmaxf(fmaf(v0.w, s_sc[kb + 3], s_sh[kb + 3]), 0.f);
            v1.x = fmaxf(fmaf(v1.x, s_sc[kb + 4], s_sh[kb + 4]), 0.f);
            v1.y = fmaxf(fmaf(v1.y, s_sc[kb + 5], s_sh[kb + 5]), 0.f);
            v1.z = fmaxf(fmaf(v1.z, s_sc[kb + 6], s_sh[kb + 6]), 0.f);
            v1.w = fmaxf(fmaf(v1.w, s_sc[kb + 7], s_sh[kb + 7]), 0.f);
            *(uint4*)&sAh[m * SK + q * 4] = make_uint4(
                packh(v0.x, v0.y), packh(v0.z, v0.w),
                packh(v1.x, v1.y), packh(v1.z, v1.w));
        }
        *(uint4*)&sBh[n * SK + qb * 4] = qh;
        __syncthreads();
        if (s < 3) {
            const float* src = g_h1 + (size_t)(tile * 128 + m) * H + (s + 1) * 32 + q * 8;
            va0 = ((const float4*)src)[0]; va1 = ((const float4*)src)[1];
            qh = *(const uint4*)&g_W2T_hi[n * 64 + (s + 1) * 16 + qb * 4];
        }
        mma_chunk_f16s(aH0, aH1, bH0, bH1, acc);
        __syncthreads();
    }

    const int odd = t4 & 1;
#pragma unroll
    for (int mt = 0; mt < 2; mt++) {
        int r0 = wm + mt * 16 + g;
#pragma unroll
        for (int nt = 0; nt < 4; nt++) {
            int c = wn + nt * 8 + 2 * t4;
            float bx = s_bias[c], by = s_bias[c + 1];
            float v00 = acc[mt][nt][0] + bx, v01 = acc[mt][nt][1] + by;
            float v10 = acc[mt][nt][2] + bx, v11 = acc[mt][nt][3] + by;
            float e0 = odd ? v00 : v10;
            float e1 = odd ? v01 : v11;
            float p0 = __shfl_xor_sync(0xffffffffu, e0, 1);
            float p1 = __shfl_xor_sync(0xffffffffu, e1, 1);
            int row = r0 + odd * 8;
            int node = colidx[row];
            int cb  = wn + nt * 8 + (t4 & 2) * 2;
            if (odd)
                red_add_v4(&g_agg[(size_t)node * H + cb], p0, p1, v10, v11);
            else
                red_add_v4(&g_agg[(size_t)node * H + cb], v00, v01, p0, p1);
        }
    }
}

// ============================================================================
// Node MMA1 (bf16x3, proven, verbatim)
// ============================================================================
__global__ __launch_bounds__(512, 1) void node_mma1(
    const float* __restrict__ x, const float* __restrict__ bias) {
    __shared__ uint32_t sAh[128 * SK], sAl[128 * SK];
    __shared__ uint32_t sBh[128 * SK], sBl[128 * SK];
    __shared__ float s_bias[128];
    __shared__ float red_s[4][128], red_q[4][128];

    const int t = threadIdx.x, tile = blockIdx.x;
    if (t < 128) s_bias[t] = bias[t];
    __syncthreads();

    const int warp = t >> 5, lane = t & 31, g = lane >> 2, t4 = lane & 3;
    const int wm = (warp >> 2) * 32, wn = (warp & 3) * 32;
    const int m = t >> 2, q = t & 3;
    const int n = t >> 2, qb = t & 3;
    const int grow = tile * 128 + m;
    const bool rok = grow < NNODES;

    const int rA = (lane & 7) + ((lane >> 3) & 1) * 8;
    const int cH = (lane >> 4) * 4;
    const uint32_t aH0 = smaddr(&sAh[(wm + rA) * SK + cH]);
    const uint32_t aH1 = smaddr(&sAh[(wm + 16 + rA) * SK + cH]);
    const uint32_t aL0 = smaddr(&sAl[(wm + rA) * SK + cH]);
    const uint32_t aL1 = smaddr(&sAl[(wm + 16 + rA) * SK + cH]);
    const int rB = lane & 15;
    const uint32_t bH0 = smaddr(&sBh[(wn + rB) * SK + cH]);
    const uint32_t bH1 = smaddr(&sBh[(wn + 16 + rB) * SK + cH]);
    const uint32_t bL0 = smaddr(&sBl[(wn + rB) * SK + cH]);
    const uint32_t bL1 = smaddr(&sBl[(wn + 16 + rB) * SK + cH]);

    float acc[2][4][4];
#pragma unroll
    for (int i = 0; i < 2; i++)
#pragma unroll
        for (int j = 0; j < 4; j++)
#pragma unroll
            for (int k = 0; k < 4; k++) acc[i][j][k] = 0.f;

    auto loadA = [&](int s, float4& v0, float4& v1) {
        if (!rok) { v0 = make_float4(0, 0, 0, 0); v1 = v0; return; }
        int k = s * 32 + q * 8;
        const float* src = (s < 2) ? (x + (size_t)grow * ND + k)
                                   : (g_agg + (size_t)grow * H + (k - 64));
        v0 = ((const float4*)src)[0]; v1 = ((const float4*)src)[1];
    };

    float4 va0, va1;
    uint4 qh, ql;
    loadA(0, va0, va1);
    qh = *(const uint4*)&g_W3T_hi[n * 96 + qb * 4];
    ql = *(const uint4*)&g_W3T_lo[n * 96 + qb * 4];

#pragma unroll
    for (int s = 0; s < 6; s++) {
        {
            uint32_t h0, l0, h1, l1, h2, l2, h3, l3;
            split2(va0.x, va0.y, h0, l0); split2(va0.z, va0.w, h1, l1);
            split2(va1.x, va1.y, h2, l2); split2(va1.z, va1.w, h3, l3);
            *(uint4*)&sAh[m * SK + q * 4] = make_uint4(h0, h1, h2, h3);
            *(uint4*)&sAl[m * SK + q * 4] = make_uint4(l0, l1, l2, l3);
        }
        {
            *(uint4*)&sBh[n * SK + qb * 4] = qh;
            *(uint4*)&sBl[n * SK + qb * 4] = ql;
        }
        __syncthreads();
        if (s < 5) {
            loadA(s + 1, va0, va1);
            qh = *(const uint4*)&g_W3T_hi[n * 96 + (s + 1) * 16 + qb * 4];
            ql = *(const uint4*)&g_W3T_lo[n * 96 + (s + 1) * 16 + qb * 4];
        }
        mma_chunk_ldsm(aH0, aH1, aL0, aL1, bH0, bH1, bL0, bL1, acc);
        __syncthreads();
    }

    float s8[8] = {0, 0, 0, 0, 0, 0, 0, 0}, q8[8] = {0, 0, 0, 0, 0, 0, 0, 0};
#pragma unroll
    for (int mt = 0; mt < 2; mt++) {
        int r0 = wm + mt * 16 + g;
        int n0 = tile * 128 + r0, n1 = n0 + 8;
        bool ok0 = n0 < NNODES, ok1 = n1 < NNODES;
#pragma unroll
        for (int nt = 0; nt < 4; nt++) {
            int c = wn + nt * 8 + 2 * t4;
            float bx = s_bias[c], by = s_bias[c + 1];
            float v00 = acc[mt][nt][0] + bx, v01 = acc[mt][nt][1] + by;
            float v10 = acc[mt][nt][2] + bx, v11 = acc[mt][nt][3] + by;
            if (ok0) {
                float2 w0 = {v00, v01};
                *(float2*)&g_h2[(size_t)n0 * H + c] = w0;
                s8[nt * 2] += v00; s8[nt * 2 + 1] += v01;
                q8[nt * 2] += v00 * v00; q8[nt * 2 + 1] += v01 * v01;
            }
            if (ok1) {
                float2 w1 = {v10, v11};
                *(float2*)&g_h2[(size_t)n1 * H + c] = w1;
                s8[nt * 2] += v10; s8[nt * 2 + 1] += v11;
                q8[nt * 2] += v10 * v10; q8[nt * 2 + 1] += v11 * v11;
            }
        }
    }
#pragma unroll
    for (int j = 0; j < 8; j++)
#pragma unroll
        for (int o = 4; o < 32; o <<= 1) {
            s8[j] += __shfl_xor_sync(0xffffffffu, s8[j], o);
            q8[j] += __shfl_xor_sync(0xffffffffu, q8[j], o);
        }
    if (lane < 4) {
        int wr = warp >> 2;
#pragma unroll
        for (int nt = 0; nt < 4; nt++) {
            red_s[wr][wn + nt * 8 + 2 * lane]     = s8[nt * 2];
            red_s[wr][wn + nt * 8 + 2 * lane + 1] = s8[nt * 2 + 1];
            red_q[wr][wn + nt * 8 + 2 * lane]     = q8[nt * 2];
            red_q[wr][wn + nt * 8 + 2 * lane + 1] = q8[nt * 2 + 1];
        }
    }
    __syncthreads();
    if (t < 128) {
        atomicAdd(&g_sum[t],   red_s[0][t] + red_s[1][t] + red_s[2][t] + red_s[3][t]);
        atomicAdd(&g_sumsq[t], red_q[0][t] + red_q[1][t] + red_q[2][t] + red_q[3][t]);
    }
}

// ============================================================================
// Node MMA2 (bf16x3, proven, verbatim)
// ============================================================================
__global__ __launch_bounds__(256, 2) void node_mma2(
    const float* __restrict__ bias, float* __restrict__ out) {
    __shared__ uint32_t sAh[128 * SK], sAl[128 * SK];
    __shared__ uint32_t sBh[64 * SK], sBl[64 * SK];
    __shared__ float s_bias[64], s_sc[128], s_sh[128];

    const int t = threadIdx.x, tile = blockIdx.x;
    if (t < 64) s_bias[t] = bias[t];
    if (t < 128) { s_sc[t] = g_scale[t]; s_sh[t] = g_shift[t]; }
    __syncthreads();

    const int warp = t >> 5, lane = t & 31, g = lane >> 2, t4 = lane & 3;
    const int wm = (warp >> 1) * 32, wn = (warp & 1) * 32;
    const int m = t >> 1, q2 = t & 1;
    const int n = t >> 2, qb = t & 3;
    const int grow = tile * 128 + m;
    const bool rok = grow < NNODES;

    const int rA = (lane & 7) + ((lane >> 3) & 1) * 8;
    const int cH = (lane >> 4) * 4;
    const uint32_t aH0 = smaddr(&sAh[(wm + rA) * SK + cH]);
    const uint32_t aH1 = smaddr(&sAh[(wm + 16 + rA) * SK + cH]);
    const uint32_t aL0 = smaddr(&sAl[(wm + rA) * SK + cH]);
    const uint32_t aL1 = smaddr(&sAl[(wm + 16 + rA) * SK + cH]);
    const int rB = lane & 15;
    const uint32_t bH0 = smaddr(&sBh[(wn + rB) * SK + cH]);
    const uint32_t bH1 = smaddr(&sBh[(wn + 16 + rB) * SK + cH]);
    const uint32_t bL0 = smaddr(&sBl[(wn + rB) * SK + cH]);
    const uint32_t bL1 = smaddr(&sBl[(wn + 16 + rB) * SK + cH]);

    float acc[2][4][4];
#pragma unroll
    for (int i = 0; i < 2; i++)
#pragma unroll
        for (int j = 0; j < 4; j++)
#pragma unroll
            for (int k = 0; k < 4; k++) acc[i][j][k] = 0.f;

    float4 va0, va1, va2, va3;
    uint4 qh, ql;
    auto loadA = [&](int s) {
        if (!rok) { va0 = make_float4(0, 0, 0, 0); va1 = va0; va2 = va0; va3 = va0; return; }
        const float* src = g_h2 + (size_t)grow * H + s * 32 + q2 * 16;
        va0 = ((const float4*)src)[0]; va1 = ((const float4*)src)[1];
        va2 = ((const float4*)src)[2]; va3 = ((const float4*)src)[3];
    };
    auto storeA = [&](int s) {
        int kb = s * 32 + q2 * 16;
        float4 v[4] = {va0, va1, va2, va3};
#pragma unroll
        for (int j = 0; j < 4; j++) {
            int k = kb + 4 * j;
            v[j].x = fmaxf(fmaf(v[j].x, s_sc[k],     s_sh[k]),     0.f);
            v[j].y = fmaxf(fmaf(v[j].y, s_sc[k + 1], s_sh[k + 1]), 0.f);
            v[j].z = fmaxf(fmaf(v[j].z, s_sc[k + 2], s_sh[k + 2]), 0.f);
            v[j].w = fmaxf(fmaf(v[j].w, s_sc[k + 3], s_sh[k + 3]), 0.f);
        }
        uint32_t h[8], l[8];
#pragma unroll
        for (int j = 0; j < 4; j++) {
            split2(v[j].x, v[j].y, h[2 * j], l[2 * j]);
            split2(v[j].z, v[j].w, h[2 * j + 1], l[2 * j + 1]);
        }
        *(uint4*)&sAh[m * SK + q2 * 8]     = make_uint4(h[0], h[1], h[2], h[3]);
        *(uint4*)&sAh[m * SK + q2 * 8 + 4] = make_uint4(h[4], h[5], h[6], h[7]);
        *(uint4*)&sAl[m * SK + q2 * 8]     = make_uint4(l[0], l[1], l[2], l[3]);
        *(uint4*)&sAl[m * SK + q2 * 8 + 4] = make_uint4(l[4], l[5], l[6], l[7]);
    };

    loadA(0);
    qh = *(const uint4*)&g_W4T_hi[n * 64 + qb * 4];
    ql = *(const uint4*)&g_W4T_lo[n * 64 + qb * 4];

#pragma unroll
    for (int s = 0; s < 4; s++) {
        storeA(s);
        *(uint4*)&sBh[n * SK + qb * 4] = qh;
        *(uint4*)&sBl[n * SK + qb * 4] = ql;
        __syncthreads();
        if (s < 3) {
            loadA(s + 1);
            qh = *(const uint4*)&g_W4T_hi[n * 64 + (s + 1) * 16 + qb * 4];
            ql = *(const uint4*)&g_W4T_lo[n * 64 + (s + 1) * 16 + qb * 4];
        }
        mma_chunk_ldsm(aH0, aH1, aL0, aL1, bH0, bH1, bL0, bL1, acc);
        __syncthreads();
    }

    const int odd = t4 & 1;
#pragma unroll
    for (int mt = 0; mt < 2; mt++) {
        int r0 = wm + mt * 16 + g;
#pragma unroll
        for (int nt = 0; nt < 4; nt++) {
            int c = wn + nt * 8 + 2 * t4;
            float bx = s_bias[c], by = s_bias[c + 1];
            float v00 = acc[mt][nt][0] + bx, v01 = acc[mt][nt][1] + by;
            float v10 = acc[mt][nt][2] + bx, v11 = acc[mt][nt][3] + by;
            float e0 = odd ? v00 : v10;
            float e1 = odd ? v01 : v11;
            float p0 = __shfl_xor_sync(0xffffffffu, e0, 1);
            float p1 = __shfl_xor_sync(0xffffffffu, e1, 1);
            int row = r0 + odd * 8;
            int gn = tile * 128 + row;
            int cb = wn + nt * 8 + (t4 & 2) * 2;
            float4 quad = odd ? make_float4(p0, p1, v10, v11)
                              : make_float4(v00, v01, p0, p1);
            if (gn < NNODES)
                *(float4*)&out[(size_t)gn * OUTD + cb] = quad;
        }
    }
}

// ============================================================================
extern "C" void kernel_launch(void* const* d_in, const int* in_sizes, int n_in,
                              void* d_out, int out_size) {
    const float* x    = (const float*)d_in[0];
    const int*   ei   = (const int*)d_in[1];
    const float* ea   = (const float*)d_in[2];
    const float* W1a  = (const float*)d_in[5];
    const float* b1a  = (const float*)d_in[6];
    const float* g1a  = (const float*)d_in[7];
    const float* be1a = (const float*)d_in[8];
    const float* W2a  = (const float*)d_in[9];
    const float* b2a  = (const float*)d_in[10];
    const float* W1b  = (const float*)d_in[11];
    const float* b1b  = (const float*)d_in[12];
    const float* g1b  = (const float*)d_in[13];
    const float* be1b = (const float*)d_in[14];
    const float* W2b  = (const float*)d_in[15];
    const float* b2b  = (const float*)d_in[16];
    float* out = (float*)d_out;

    prep_kernel<<<(NNODES * H / 4 + 255) / 256, 256>>>(W1a, W2a, W1b, W2b);
    edge_mma1<<<NTILES2, 512>>>(x, ei, ea, b1a);
    finalize_bn<<<1, 128>>>(g1a, be1a, 1.0f / (float)NEDGES);
    edge_mma2<<<NTILES2, 512>>>(ei, b2a);
    node_mma1<<<NODE_TILES, 512>>>(x, b1b);
    finalize_bn<<<1, 128>>>(g1b, be1b, 1.0f / (float)NNODES);
    node_mma2<<<NODE_TILES, 256>>>(b2b, out);
}